// round 2
// baseline (speedup 1.0000x reference)
#include <cuda_runtime.h>
#include <cuda_bf16.h>
#include <math.h>

// ---------------------------------------------------------------------------
// MIGAttention: gate -> top-k mask -> GQA attention -> output projection
// B=4, N=2048, C=1024, H=16, HKV=4, DH=64, KEEP=0.7 -> k_keep=1433
// ---------------------------------------------------------------------------

#define Bq 4
#define Nq 2048
#define Cq 1024
#define Hq 16
#define HKVq 4
#define DHq 64
#define TOK (Bq*Nq)          // 8192
#define KKEEP 1433

// scratch layout (floats):
//  xg  : 0                .. 8M
//  q   : 8M               .. 16M
//  k   : 16M              .. 18M
//  v   : 18M              .. 20M
//  o   : 20M              .. 28M
//  gate: 28M              .. 28M+8192
//  thr : 28M+8192         .. +4
#define SCRATCH_FLOATS (28u*1024u*1024u + 8192u + 4u)
__device__ __align__(256) float g_scratch[SCRATCH_FLOATS];

// ---------------------------------------------------------------------------
// gate[token] = sigmoid(dot(x[token,:], router_w) + router_b)
// one warp per token
// ---------------------------------------------------------------------------
__global__ __launch_bounds__(256) void gate_kernel(
    const float* __restrict__ x, const float* __restrict__ rw,
    const float* __restrict__ rb, float* __restrict__ gate)
{
    int warp = threadIdx.x >> 5, lane = threadIdx.x & 31;
    int token = blockIdx.x * 8 + warp;
    const float* xr = x + (size_t)token * Cq;
    float s = 0.f;
    #pragma unroll 8
    for (int i = lane; i < Cq; i += 32) s += xr[i] * rw[i];
    #pragma unroll
    for (int o = 16; o; o >>= 1) s += __shfl_xor_sync(0xffffffffu, s, o);
    if (lane == 0) {
        float z = s + rb[0];
        gate[token] = 1.f / (1.f + expf(-z));
    }
}

// ---------------------------------------------------------------------------
// per-batch bitonic sort (descending) of 2048 gate scores; threshold = s[KKEEP-1]
// ---------------------------------------------------------------------------
__global__ __launch_bounds__(1024) void topk_kernel(
    const float* __restrict__ gate, float* __restrict__ thr)
{
    __shared__ float s[2048];
    int b = blockIdx.x, t = threadIdx.x;
    s[t]        = gate[b * Nq + t];
    s[t + 1024] = gate[b * Nq + t + 1024];
    __syncthreads();
    for (int k2 = 2; k2 <= 2048; k2 <<= 1) {
        for (int j = k2 >> 1; j > 0; j >>= 1) {
            #pragma unroll
            for (int rep = 0; rep < 2; rep++) {
                int i = t + rep * 1024;
                int ixj = i ^ j;
                if (ixj > i) {
                    bool desc = ((i & k2) == 0);
                    float a = s[i], c = s[ixj];
                    if (desc ? (a < c) : (a > c)) { s[i] = c; s[ixj] = a; }
                }
            }
            __syncthreads();
        }
    }
    if (t == 0) thr[b] = s[KKEEP - 1];
}

// ---------------------------------------------------------------------------
// xg = x * gate * (gate >= thresh[b])   (float4 elementwise)
// ---------------------------------------------------------------------------
__global__ __launch_bounds__(256) void xg_kernel(
    const float4* __restrict__ x, const float* __restrict__ gate,
    const float* __restrict__ thr, float4* __restrict__ xg)
{
    int i = blockIdx.x * 256 + threadIdx.x;   // 2M float4
    int token = i >> 8;                        // 256 float4 per token
    int b = token >> 11;
    float g = gate[token];
    g = (g >= thr[b]) ? g : 0.f;
    float4 v = x[i];
    v.x *= g; v.y *= g; v.z *= g; v.w *= g;
    xg[i] = v;
}

// ---------------------------------------------------------------------------
// SGEMM: C[M,N] = A[M,K] @ B[K,N] + bias[N]
// 128x128 block tile, Ktile=8, 256 threads, 8x8 per thread
// M,N,K all multiples of tile sizes here (no bounds checks)
// ---------------------------------------------------------------------------
__global__ __launch_bounds__(256) void sgemm128(
    const float* __restrict__ A, const float* __restrict__ B,
    const float* __restrict__ bias, float* __restrict__ C,
    int M, int N, int K)
{
    __shared__ float As[8][128];
    __shared__ float Bs[8][128];
    const int t = threadIdx.x;
    const int bn = blockIdx.x, bm = blockIdx.y;
    const int tx = t & 15, ty = t >> 4;
    const int arow = t >> 1, acol = (t & 1) << 2;
    const int brow = t >> 5, bcol = (t & 31) << 2;
    const float* Ap = A + (size_t)(bm * 128 + arow) * K + acol;
    const float* Bp = B + (size_t)brow * N + bn * 128 + bcol;

    float acc[8][8];
    #pragma unroll
    for (int i = 0; i < 8; i++)
        #pragma unroll
        for (int j = 0; j < 8; j++) acc[i][j] = 0.f;

    for (int k0 = 0; k0 < K; k0 += 8) {
        float4 av = *(const float4*)Ap; Ap += 8;
        float4 bv = *(const float4*)Bp; Bp += (size_t)8 * N;
        As[acol + 0][arow] = av.x;
        As[acol + 1][arow] = av.y;
        As[acol + 2][arow] = av.z;
        As[acol + 3][arow] = av.w;
        *(float4*)&Bs[brow][bcol] = bv;
        __syncthreads();
        #pragma unroll
        for (int kk = 0; kk < 8; kk++) {
            float4 a0 = *(const float4*)&As[kk][ty << 2];
            float4 a1 = *(const float4*)&As[kk][64 + (ty << 2)];
            float4 b0 = *(const float4*)&Bs[kk][tx << 2];
            float4 b1 = *(const float4*)&Bs[kk][64 + (tx << 2)];
            float a[8]  = {a0.x, a0.y, a0.z, a0.w, a1.x, a1.y, a1.z, a1.w};
            float bb[8] = {b0.x, b0.y, b0.z, b0.w, b1.x, b1.y, b1.z, b1.w};
            #pragma unroll
            for (int i = 0; i < 8; i++)
                #pragma unroll
                for (int j = 0; j < 8; j++)
                    acc[i][j] += a[i] * bb[j];
        }
        __syncthreads();
    }
    #pragma unroll
    for (int i = 0; i < 8; i++) {
        int row = bm * 128 + ((i < 4) ? (ty * 4 + i) : (64 + ty * 4 + i - 4));
        #pragma unroll
        for (int j = 0; j < 8; j++) {
            int col = bn * 128 + ((j < 4) ? (tx * 4 + j) : (64 + tx * 4 + j - 4));
            C[(size_t)row * N + col] = acc[i][j] + bias[col];
        }
    }
}

// ---------------------------------------------------------------------------
// Flash attention (fp32): per block handles (b, h, 64-row q tile)
// Q layout (B,N,H,DH), K/V layout (B,N,HKV,DH), O layout (B*N, C) with col=h*64+d
// smem: Qs[d][r] (64x68), KVs (K as [d][c], V as [c][d]) (64x68), Ss[c][r] (64x68)
// NOTE: SPAD must be a multiple of 4 so float4 smem accesses stay 16B-aligned.
// ---------------------------------------------------------------------------
#define SPAD 68
#define ATTN_SMEM ((3 * 64 * SPAD + 3 * 64) * 4)

__global__ __launch_bounds__(256) void attn_kernel(
    const float* __restrict__ Q, const float* __restrict__ Kb,
    const float* __restrict__ Vb, float* __restrict__ O)
{
    extern __shared__ float sm[];
    float* Qs   = sm;
    float* KVs  = sm + 64 * SPAD;
    float* Ss   = sm + 2 * 64 * SPAD;
    float* rowm = sm + 3 * 64 * SPAD;
    float* rowl = rowm + 64;
    float* rowsc = rowl + 64;

    const int t = threadIdx.x;
    const int qt = blockIdx.x, h = blockIdx.y, b = blockIdx.z;
    const int hkv = h >> 2;
    const int tx = t & 15, ty = t >> 4;

    // load Q tile transposed: Qs[d*SPAD + r]
    const float* qbase = Q + ((size_t)(b * Nq + qt * 64) * Hq + h) * DHq;
    for (int idx = t; idx < 4096; idx += 256) {
        int r = idx >> 6, d = idx & 63;
        Qs[d * SPAD + r] = qbase[(size_t)r * (Hq * DHq) + d];
    }
    if (t < 64) { rowm[t] = -1e30f; rowl[t] = 0.f; }

    float oacc[4][4];
    #pragma unroll
    for (int i = 0; i < 4; i++)
        #pragma unroll
        for (int j = 0; j < 4; j++) oacc[i][j] = 0.f;

    __syncthreads();

    const float* kbase = Kb + ((size_t)b * Nq * HKVq + hkv) * DHq;
    const float* vbase = Vb + ((size_t)b * Nq * HKVq + hkv) * DHq;

    for (int kt = 0; kt < 32; kt++) {
        // K tile transposed: KVs[d*SPAD + c]
        for (int idx = t; idx < 4096; idx += 256) {
            int c = idx >> 6, d = idx & 63;
            KVs[d * SPAD + c] = kbase[(size_t)(kt * 64 + c) * (HKVq * DHq) + d];
        }
        __syncthreads();

        // S = Q K^T * 0.125 : thread computes rows ty*4.., cols tx*4..
        float s[4][4];
        #pragma unroll
        for (int i = 0; i < 4; i++)
            #pragma unroll
            for (int j = 0; j < 4; j++) s[i][j] = 0.f;

        #pragma unroll 8
        for (int d = 0; d < 64; d++) {
            float4 a4 = *(const float4*)&Qs[d * SPAD + (ty << 2)];
            float4 k4 = *(const float4*)&KVs[d * SPAD + (tx << 2)];
            float a[4] = {a4.x, a4.y, a4.z, a4.w};
            float k[4] = {k4.x, k4.y, k4.z, k4.w};
            #pragma unroll
            for (int i = 0; i < 4; i++)
                #pragma unroll
                for (int j = 0; j < 4; j++)
                    s[i][j] += a[i] * k[j];
        }
        // store S as [c][r]
        #pragma unroll
        for (int j = 0; j < 4; j++)
            #pragma unroll
            for (int i = 0; i < 4; i++)
                Ss[(tx * 4 + j) * SPAD + ty * 4 + i] = s[i][j] * 0.125f;
        __syncthreads();

        // online softmax row pass (2 warps) overlapped with V tile load (all threads)
        if (t < 64) {
            float mold = rowm[t];
            float mx = mold;
            #pragma unroll 8
            for (int c = 0; c < 64; c++) mx = fmaxf(mx, Ss[c * SPAD + t]);
            float sc = __expf(mold - mx);
            float sum = 0.f;
            #pragma unroll 8
            for (int c = 0; c < 64; c++) {
                float p = __expf(Ss[c * SPAD + t] - mx);
                Ss[c * SPAD + t] = p;
                sum += p;
            }
            rowl[t] = rowl[t] * sc + sum;
            rowm[t] = mx;
            rowsc[t] = sc;
        }
        // V tile: KVs[c*SPAD + d]
        for (int idx = t; idx < 4096; idx += 256) {
            int c = idx >> 6, d = idx & 63;
            KVs[c * SPAD + d] = vbase[(size_t)(kt * 64 + c) * (HKVq * DHq) + d];
        }
        __syncthreads();

        // rescale O, then O += P V
        float rs[4];
        #pragma unroll
        for (int i = 0; i < 4; i++) rs[i] = rowsc[ty * 4 + i];
        #pragma unroll
        for (int i = 0; i < 4; i++)
            #pragma unroll
            for (int j = 0; j < 4; j++) oacc[i][j] *= rs[i];

        #pragma unroll 8
        for (int c = 0; c < 64; c++) {
            float4 p4 = *(const float4*)&Ss[c * SPAD + (ty << 2)];
            float4 v4 = *(const float4*)&KVs[c * SPAD + (tx << 2)];
            float p[4] = {p4.x, p4.y, p4.z, p4.w};
            float v[4] = {v4.x, v4.y, v4.z, v4.w};
            #pragma unroll
            for (int i = 0; i < 4; i++)
                #pragma unroll
                for (int j = 0; j < 4; j++)
                    oacc[i][j] += p[i] * v[j];
        }
        __syncthreads();
    }

    // epilogue: O / l, write to (token, h*64+d)
    float rl[4];
    #pragma unroll
    for (int i = 0; i < 4; i++) rl[i] = 1.f / rowl[ty * 4 + i];
    #pragma unroll
    for (int i = 0; i < 4; i++) {
        size_t row = (size_t)(b * Nq + qt * 64 + ty * 4 + i);
        #pragma unroll
        for (int j = 0; j < 4; j++) {
            O[row * Cq + h * DHq + tx * 4 + j] = oacc[i][j] * rl[i];
        }
    }
}

// ---------------------------------------------------------------------------
extern "C" void kernel_launch(void* const* d_in, const int* in_sizes, int n_in,
                              void* d_out, int out_size)
{
    const float* x   = (const float*)d_in[0];
    const float* rw  = (const float*)d_in[1];
    const float* rb  = (const float*)d_in[2];
    const float* wq  = (const float*)d_in[3];
    const float* bq  = (const float*)d_in[4];
    const float* wk  = (const float*)d_in[5];
    const float* bk  = (const float*)d_in[6];
    const float* wv  = (const float*)d_in[7];
    const float* bv  = (const float*)d_in[8];
    const float* wo  = (const float*)d_in[9];
    const float* bo  = (const float*)d_in[10];
    float* out = (float*)d_out;

    float* base;
    cudaGetSymbolAddress((void**)&base, g_scratch);
    float* xg   = base;
    float* qb   = base + 8u * 1024u * 1024u;
    float* kb   = base + 16u * 1024u * 1024u;
    float* vb   = base + 18u * 1024u * 1024u;
    float* ob   = base + 20u * 1024u * 1024u;
    float* gate = base + 28u * 1024u * 1024u;
    float* thr  = gate + 8192;

    cudaFuncSetAttribute(attn_kernel, cudaFuncAttributeMaxDynamicSharedMemorySize, ATTN_SMEM);

    gate_kernel<<<TOK / 8, 256>>>(x, rw, rb, gate);
    topk_kernel<<<Bq, 1024>>>(gate, thr);
    xg_kernel<<<(TOK * Cq) / (4 * 256), 256>>>((const float4*)x, gate, thr, (float4*)xg);

    sgemm128<<<dim3(Cq / 128, TOK / 128), 256>>>(xg, wq, bq, qb, TOK, Hq * DHq, Cq);
    sgemm128<<<dim3((HKVq * DHq) / 128, TOK / 128), 256>>>(xg, wk, bk, kb, TOK, HKVq * DHq, Cq);
    sgemm128<<<dim3((HKVq * DHq) / 128, TOK / 128), 256>>>(xg, wv, bv, vb, TOK, HKVq * DHq, Cq);

    attn_kernel<<<dim3(Nq / 64, Hq, Bq), 256, ATTN_SMEM>>>(qb, kb, vb, ob);

    sgemm128<<<dim3(Cq / 128, TOK / 128), 256>>>(ob, wo, bo, out, TOK, Cq, Cq);
}

// round 3
// speedup vs baseline: 1.1049x; 1.1049x over previous
#include <cuda_runtime.h>
#include <cuda_bf16.h>
#include <math.h>

// ---------------------------------------------------------------------------
// MIGAttention: gate -> top-k mask -> GQA attention -> output projection
// B=4, N=2048, C=1024, H=16, HKV=4, DH=64, KEEP=0.7 -> k_keep=1433
// ---------------------------------------------------------------------------

#define Bq 4
#define Nq 2048
#define Cq 1024
#define Hq 16
#define HKVq 4
#define DHq 64
#define TOK (Bq*Nq)          // 8192
#define KKEEP 1433

// scratch layout (floats)
#define XG_OFF   0u
#define QKV_OFF  8388608u                   // 8192*1536 = 12582912
#define OB_OFF   (QKV_OFF + 12582912u)      // 8192*1024 = 8388608
#define WQKV_OFF (OB_OFF + 8388608u)        // 1024*1536 = 1572864
#define BQKV_OFF (WQKV_OFF + 1572864u)      // 1536
#define GATE_OFF (BQKV_OFF + 1536u)         // 8192
#define THR_OFF  (GATE_OFF + 8192u)         // 4
#define SCRATCH_FLOATS (THR_OFF + 4u)
__device__ __align__(256) float g_scratch[SCRATCH_FLOATS];

__device__ __forceinline__ void cp_async16(void* smem, const void* gmem) {
    unsigned s = (unsigned)__cvta_generic_to_shared(smem);
    asm volatile("cp.async.cg.shared.global [%0], [%1], 16;\n" :: "r"(s), "l"(gmem));
}
#define CP_COMMIT asm volatile("cp.async.commit_group;\n" ::: "memory")
#define CP_WAIT0  asm volatile("cp.async.wait_group 0;\n" ::: "memory")

__device__ __forceinline__ float ex2(float x) {
    float y; asm("ex2.approx.f32 %0, %1;" : "=f"(y) : "f"(x)); return y;
}

// ---------------------------------------------------------------------------
// gate[token] = sigmoid(dot(x[token,:], router_w) + router_b); one warp/token
// ---------------------------------------------------------------------------
__global__ __launch_bounds__(256) void gate_kernel(
    const float* __restrict__ x, const float* __restrict__ rw,
    const float* __restrict__ rb, float* __restrict__ gate)
{
    int warp = threadIdx.x >> 5, lane = threadIdx.x & 31;
    int token = blockIdx.x * 8 + warp;
    const float* xr = x + (size_t)token * Cq;
    float s = 0.f;
    #pragma unroll 8
    for (int i = lane; i < Cq; i += 32) s += xr[i] * rw[i];
    #pragma unroll
    for (int o = 16; o; o >>= 1) s += __shfl_xor_sync(0xffffffffu, s, o);
    if (lane == 0) {
        float z = s + rb[0];
        gate[token] = 1.f / (1.f + expf(-z));
    }
}

// ---------------------------------------------------------------------------
// per-batch bitonic sort (descending); threshold = s[KKEEP-1]
// ---------------------------------------------------------------------------
__global__ __launch_bounds__(1024) void topk_kernel(
    const float* __restrict__ gate, float* __restrict__ thr)
{
    __shared__ float s[2048];
    int b = blockIdx.x, t = threadIdx.x;
    s[t]        = gate[b * Nq + t];
    s[t + 1024] = gate[b * Nq + t + 1024];
    __syncthreads();
    for (int k2 = 2; k2 <= 2048; k2 <<= 1) {
        for (int j = k2 >> 1; j > 0; j >>= 1) {
            #pragma unroll
            for (int rep = 0; rep < 2; rep++) {
                int i = t + rep * 1024;
                int ixj = i ^ j;
                if (ixj > i) {
                    bool desc = ((i & k2) == 0);
                    float a = s[i], c = s[ixj];
                    if (desc ? (a < c) : (a > c)) { s[i] = c; s[ixj] = a; }
                }
            }
            __syncthreads();
        }
    }
    if (t == 0) thr[b] = s[KKEEP - 1];
}

// ---------------------------------------------------------------------------
// xg = x * gate * (gate >= thresh[b])
// ---------------------------------------------------------------------------
__global__ __launch_bounds__(256) void xg_kernel(
    const float4* __restrict__ x, const float* __restrict__ gate,
    const float* __restrict__ thr, float4* __restrict__ xg)
{
    int i = blockIdx.x * 256 + threadIdx.x;
    int token = i >> 8;
    int b = token >> 11;
    float g = gate[token];
    g = (g >= thr[b]) ? g : 0.f;
    float4 v = x[i];
    v.x *= g; v.y *= g; v.z *= g; v.w *= g;
    xg[i] = v;
}

// ---------------------------------------------------------------------------
// pack wq|wk|wv -> [1024,1536], bq|bk|bv -> [1536]
// ---------------------------------------------------------------------------
__global__ __launch_bounds__(256) void pack_kernel(
    const float* __restrict__ wq, const float* __restrict__ wk,
    const float* __restrict__ wv, const float* __restrict__ bq,
    const float* __restrict__ bk, const float* __restrict__ bv,
    float* __restrict__ wqkv, float* __restrict__ bqkv)
{
    int idx = blockIdx.x * 256 + threadIdx.x;   // 1024*384 float4
    int r = idx / 384, c4 = (idx % 384) * 4;
    float4 v;
    if (c4 < 1024)       v = *(const float4*)(wq + (size_t)r * 1024 + c4);
    else if (c4 < 1280)  v = *(const float4*)(wk + (size_t)r * 256 + (c4 - 1024));
    else                 v = *(const float4*)(wv + (size_t)r * 256 + (c4 - 1280));
    *(float4*)(wqkv + (size_t)r * 1536 + c4) = v;
    if (idx < 1536) {
        float bb;
        if (idx < 1024)      bb = bq[idx];
        else if (idx < 1280) bb = bk[idx - 1024];
        else                 bb = bv[idx - 1280];
        bqkv[idx] = bb;
    }
}

// ---------------------------------------------------------------------------
// SGEMM: C[M,N] = A[M,K] @ B[K,N] + bias[N]
// 128x128 tile, Ktile=16, double-buffered smem, cp.async for B
// ---------------------------------------------------------------------------
__global__ __launch_bounds__(256) void sgemm_db(
    const float* __restrict__ A, const float* __restrict__ B,
    const float* __restrict__ bias, float* __restrict__ C,
    int M, int N, int K)
{
    __shared__ float As[2][16][128];
    __shared__ float Bs[2][16][128];
    const int t = threadIdx.x;
    const int bn = blockIdx.x, bm = blockIdx.y;
    const int tx = t & 15, ty = t >> 4;
    const int am = t >> 1, ak = (t & 1) * 8;
    const float* Ap = A + (size_t)(bm * 128 + am) * K + ak;
    const int brow = t >> 4, bcol = (t & 15) * 4;
    const float* Bp = B + (size_t)brow * N + bn * 128 + bcol;

    // preload tile 0
    {
        float4 a0 = *(const float4*)(Ap);
        float4 a1 = *(const float4*)(Ap + 4);
        #pragma unroll
        for (int u = 0; u < 4; u++) {
            As[0][ak + u][am]     = ((float*)&a0)[u];
            As[0][ak + 4 + u][am] = ((float*)&a1)[u];
        }
        cp_async16(&Bs[0][brow][bcol], Bp);
        cp_async16(&Bs[0][brow][bcol + 64], Bp + 64);
        CP_COMMIT; CP_WAIT0;
    }
    __syncthreads();

    float acc[8][8];
    #pragma unroll
    for (int i = 0; i < 8; i++)
        #pragma unroll
        for (int j = 0; j < 8; j++) acc[i][j] = 0.f;

    const int nt = K / 16;
    for (int kt = 0; kt < nt; kt++) {
        const int cur = kt & 1, nxt = cur ^ 1;
        float4 na0, na1;
        bool pf = (kt + 1 < nt);
        if (pf) {
            const float* Ap2 = Ap + (kt + 1) * 16;
            na0 = *(const float4*)(Ap2);
            na1 = *(const float4*)(Ap2 + 4);
            const float* Bp2 = Bp + (size_t)(kt + 1) * 16 * N;
            cp_async16(&Bs[nxt][brow][bcol], Bp2);
            cp_async16(&Bs[nxt][brow][bcol + 64], Bp2 + 64);
            CP_COMMIT;
        }
        #pragma unroll
        for (int kk = 0; kk < 16; kk++) {
            float4 a0 = *(const float4*)&As[cur][kk][ty << 2];
            float4 a1 = *(const float4*)&As[cur][kk][64 + (ty << 2)];
            float4 b0 = *(const float4*)&Bs[cur][kk][tx << 2];
            float4 b1 = *(const float4*)&Bs[cur][kk][64 + (tx << 2)];
            float a[8]  = {a0.x, a0.y, a0.z, a0.w, a1.x, a1.y, a1.z, a1.w};
            float bb[8] = {b0.x, b0.y, b0.z, b0.w, b1.x, b1.y, b1.z, b1.w};
            #pragma unroll
            for (int i = 0; i < 8; i++)
                #pragma unroll
                for (int j = 0; j < 8; j++)
                    acc[i][j] += a[i] * bb[j];
        }
        if (pf) {
            #pragma unroll
            for (int u = 0; u < 4; u++) {
                As[nxt][ak + u][am]     = ((float*)&na0)[u];
                As[nxt][ak + 4 + u][am] = ((float*)&na1)[u];
            }
            CP_WAIT0;
        }
        __syncthreads();
    }
    #pragma unroll
    for (int i = 0; i < 8; i++) {
        int row = bm * 128 + ((i < 4) ? (ty * 4 + i) : (64 + ty * 4 + i - 4));
        #pragma unroll
        for (int j = 0; j < 8; j++) {
            int col = bn * 128 + ((j < 4) ? (tx * 4 + j) : (64 + tx * 4 + j - 4));
            C[(size_t)row * N + col] = acc[i][j] + bias[col];
        }
    }
}

// ---------------------------------------------------------------------------
// Flash attention fp32 v2: register softmax (16-lane shfl), cp.async V,
// double-buffered K (LDG prefetch + transposed STS), P stored once via STS.128.
// QKV packed layout: row = token (stride 1536): q at h*64, k at 1024+hkv*64,
// v at 1280+hkv*64. O: [TOK][1024], col = h*64+d.
// ---------------------------------------------------------------------------
#define SPAD 68
#define ATTN_SMEM (5 * 64 * SPAD * 4)
#define LOG2E 1.4426950408889634f

__global__ __launch_bounds__(256, 2) void attn2(
    const float* __restrict__ QKV, float* __restrict__ O)
{
    extern __shared__ float sm[];
    float* Qs  = sm;                 // [d][r]
    float* Ks0 = sm + 64 * SPAD;     // [d][c]
    float* Ks1 = Ks0 + 64 * SPAD;
    float* Vs  = Ks1 + 64 * SPAD;    // [c][d]
    float* Ss  = Vs + 64 * SPAD;     // [r][c]  (P)

    const int t = threadIdx.x;
    const int tx = t & 15, ty = t >> 4;
    const int qt = blockIdx.x, h = blockIdx.y, b = blockIdx.z;
    const int hkv = h >> 2;

    const float* qbase = QKV + (size_t)(b * Nq + qt * 64) * 1536 + h * 64;
    const float* kbase = QKV + (size_t)b * Nq * 1536 + 1024 + hkv * 64;
    const float* vbase = kbase + 256;

    const float QSC = 0.125f * LOG2E;

    // load Q transposed & scaled
    for (int idx = t; idx < 4096; idx += 256) {
        int r = idx >> 6, d = idx & 63;
        Qs[d * SPAD + r] = qbase[(size_t)r * 1536 + d] * QSC;
    }
    // preload K tile 0 (transposed)
    {
        #pragma unroll
        for (int l = 0; l < 4; l++) {
            int e = t + l * 256; int c = e >> 4; int d4 = (e & 15) * 4;
            float4 kv = *(const float4*)(kbase + (size_t)c * 1536 + d4);
            Ks0[(d4 + 0) * SPAD + c] = kv.x;
            Ks0[(d4 + 1) * SPAD + c] = kv.y;
            Ks0[(d4 + 2) * SPAD + c] = kv.z;
            Ks0[(d4 + 3) * SPAD + c] = kv.w;
        }
    }
    float m_[4], l_[4], oacc[4][4];
    #pragma unroll
    for (int i = 0; i < 4; i++) {
        m_[i] = -1e30f; l_[i] = 0.f;
        #pragma unroll
        for (int j = 0; j < 4; j++) oacc[i][j] = 0.f;
    }
    __syncthreads();

    for (int kt = 0; kt < 32; kt++) {
        float* Kc = (kt & 1) ? Ks1 : Ks0;
        float* Kn = (kt & 1) ? Ks0 : Ks1;

        // issue V[kt] async copy into Vs
        #pragma unroll
        for (int l = 0; l < 4; l++) {
            int e = t + l * 256; int c = e >> 4; int d4 = (e & 15) * 4;
            cp_async16(&Vs[c * SPAD + d4],
                       vbase + (size_t)(kt * 64 + c) * 1536 + d4);
        }
        CP_COMMIT;

        // prefetch next K tile into regs
        float4 kr[4];
        if (kt < 31) {
            #pragma unroll
            for (int l = 0; l < 4; l++) {
                int e = t + l * 256; int c = e >> 4; int d4 = (e & 15) * 4;
                kr[l] = *(const float4*)(kbase + (size_t)((kt + 1) * 64 + c) * 1536 + d4);
            }
        }

        // S = Q^T K (already log2-scaled)
        float s[4][4];
        #pragma unroll
        for (int i = 0; i < 4; i++)
            #pragma unroll
            for (int j = 0; j < 4; j++) s[i][j] = 0.f;
        #pragma unroll 8
        for (int d = 0; d < 64; d++) {
            float4 q4 = *(const float4*)&Qs[d * SPAD + (ty << 2)];
            float4 k4 = *(const float4*)&Kc[d * SPAD + (tx << 2)];
            float a[4] = {q4.x, q4.y, q4.z, q4.w};
            float k[4] = {k4.x, k4.y, k4.z, k4.w};
            #pragma unroll
            for (int i = 0; i < 4; i++)
                #pragma unroll
                for (int j = 0; j < 4; j++)
                    s[i][j] += a[i] * k[j];
        }

        // stash next K
        if (kt < 31) {
            #pragma unroll
            for (int l = 0; l < 4; l++) {
                int e = t + l * 256; int c = e >> 4; int d4 = (e & 15) * 4;
                Kn[(d4 + 0) * SPAD + c] = kr[l].x;
                Kn[(d4 + 1) * SPAD + c] = kr[l].y;
                Kn[(d4 + 2) * SPAD + c] = kr[l].z;
                Kn[(d4 + 3) * SPAD + c] = kr[l].w;
            }
        }

        // online softmax in registers (rows spread across 16-lane tx groups)
        #pragma unroll
        for (int i = 0; i < 4; i++) {
            float mx = fmaxf(fmaxf(s[i][0], s[i][1]), fmaxf(s[i][2], s[i][3]));
            #pragma unroll
            for (int o = 1; o < 16; o <<= 1)
                mx = fmaxf(mx, __shfl_xor_sync(0xffffffffu, mx, o, 16));
            float mnew = fmaxf(m_[i], mx);
            float sc = ex2(m_[i] - mnew);
            float sum = 0.f;
            #pragma unroll
            for (int j = 0; j < 4; j++) {
                float p = ex2(s[i][j] - mnew);
                s[i][j] = p;
                sum += p;
            }
            #pragma unroll
            for (int o = 1; o < 16; o <<= 1)
                sum += __shfl_xor_sync(0xffffffffu, sum, o, 16);
            l_[i] = l_[i] * sc + sum;
            m_[i] = mnew;
            #pragma unroll
            for (int j = 0; j < 4; j++) oacc[i][j] *= sc;
        }

        // store P row-major
        #pragma unroll
        for (int i = 0; i < 4; i++)
            *(float4*)&Ss[(ty * 4 + i) * SPAD + (tx << 2)] =
                make_float4(s[i][0], s[i][1], s[i][2], s[i][3]);

        CP_WAIT0;
        __syncthreads();

        // O += P V
        #pragma unroll 4
        for (int c0 = 0; c0 < 64; c0 += 4) {
            float4 pr[4];
            #pragma unroll
            for (int i = 0; i < 4; i++)
                pr[i] = *(const float4*)&Ss[(ty * 4 + i) * SPAD + c0];
            #pragma unroll
            for (int jc = 0; jc < 4; jc++) {
                float4 vv = *(const float4*)&Vs[(c0 + jc) * SPAD + (tx << 2)];
                #pragma unroll
                for (int i = 0; i < 4; i++) {
                    float p = ((const float*)&pr[i])[jc];
                    oacc[i][0] += p * vv.x;
                    oacc[i][1] += p * vv.y;
                    oacc[i][2] += p * vv.z;
                    oacc[i][3] += p * vv.w;
                }
            }
        }
        __syncthreads();
    }

    // epilogue
    #pragma unroll
    for (int i = 0; i < 4; i++) {
        float rl = 1.f / l_[i];
        size_t row = (size_t)(b * Nq + qt * 64 + ty * 4 + i);
        *(float4*)&O[row * Cq + h * 64 + (tx << 2)] =
            make_float4(oacc[i][0] * rl, oacc[i][1] * rl,
                        oacc[i][2] * rl, oacc[i][3] * rl);
    }
}

// ---------------------------------------------------------------------------
extern "C" void kernel_launch(void* const* d_in, const int* in_sizes, int n_in,
                              void* d_out, int out_size)
{
    const float* x   = (const float*)d_in[0];
    const float* rw  = (const float*)d_in[1];
    const float* rb  = (const float*)d_in[2];
    const float* wq  = (const float*)d_in[3];
    const float* bq  = (const float*)d_in[4];
    const float* wk  = (const float*)d_in[5];
    const float* bk  = (const float*)d_in[6];
    const float* wv  = (const float*)d_in[7];
    const float* bv  = (const float*)d_in[8];
    const float* wo  = (const float*)d_in[9];
    const float* bo  = (const float*)d_in[10];
    float* out = (float*)d_out;

    float* base;
    cudaGetSymbolAddress((void**)&base, g_scratch);
    float* xg   = base + XG_OFF;
    float* qkv  = base + QKV_OFF;
    float* ob   = base + OB_OFF;
    float* wqkv = base + WQKV_OFF;
    float* bqkv = base + BQKV_OFF;
    float* gate = base + GATE_OFF;
    float* thr  = base + THR_OFF;

    cudaFuncSetAttribute(attn2, cudaFuncAttributeMaxDynamicSharedMemorySize, ATTN_SMEM);

    gate_kernel<<<TOK / 8, 256>>>(x, rw, rb, gate);
    topk_kernel<<<Bq, 1024>>>(gate, thr);
    xg_kernel<<<(TOK * Cq) / (4 * 256), 256>>>((const float4*)x, gate, thr, (float4*)xg);
    pack_kernel<<<(1024 * 384) / 256, 256>>>(wq, wk, wv, bq, bk, bv, wqkv, bqkv);

    // fused QKV projection: [8192,1024] @ [1024,1536]
    sgemm_db<<<dim3(1536 / 128, TOK / 128), 256>>>(xg, wqkv, bqkv, qkv, TOK, 1536, Cq);

    attn2<<<dim3(Nq / 64, Hq, Bq), 256, ATTN_SMEM>>>(qkv, ob);

    // output projection
    sgemm_db<<<dim3(Cq / 128, TOK / 128), 256>>>(ob, wo, bo, out, TOK, Cq, Cq);
}

// round 4
// speedup vs baseline: 3.0765x; 2.7843x over previous
#include <cuda_runtime.h>
#include <cuda_bf16.h>
#include <math.h>

// ---------------------------------------------------------------------------
// MIGAttention: gate -> top-k mask -> GQA attention -> output projection
// B=4, N=2048, C=1024, H=16, HKV=4, DH=64, KEEP=0.7 -> k_keep=1433
// All matmuls on tensor cores: mma.sync m16n8k8 tf32 (cvt.rna fragments).
// ---------------------------------------------------------------------------

#define Bq 4
#define Nq 2048
#define Cq 1024
#define Hq 16
#define HKVq 4
#define DHq 64
#define TOK (Bq*Nq)          // 8192
#define KKEEP 1433
#define LOG2E 1.4426950408889634f

// scratch layout (floats)
#define XG_OFF   0u
#define QKV_OFF  8388608u                   // 8192*1536 = 12582912
#define OB_OFF   (QKV_OFF + 12582912u)      // 8192*1024 = 8388608
#define WQKV_OFF (OB_OFF + 8388608u)        // 1024*1536 = 1572864
#define BQKV_OFF (WQKV_OFF + 1572864u)      // 1536
#define GATE_OFF (BQKV_OFF + 1536u)         // 8192
#define THR_OFF  (GATE_OFF + 8192u)         // 4
#define SCRATCH_FLOATS (THR_OFF + 4u)
__device__ __align__(256) float g_scratch[SCRATCH_FLOATS];

__device__ __forceinline__ void cp_async16(void* smem, const void* gmem) {
    unsigned s = (unsigned)__cvta_generic_to_shared(smem);
    asm volatile("cp.async.cg.shared.global [%0], [%1], 16;\n" :: "r"(s), "l"(gmem));
}
#define CP_COMMIT asm volatile("cp.async.commit_group;\n" ::: "memory")
#define CP_WAIT0  asm volatile("cp.async.wait_group 0;\n" ::: "memory")

__device__ __forceinline__ float ex2(float x) {
    float y; asm("ex2.approx.f32 %0, %1;" : "=f"(y) : "f"(x)); return y;
}
// round fp32 -> tf32 (result is fp32-bit-pattern with 10-bit mantissa, rna)
__device__ __forceinline__ unsigned f2tf(float x) {
    unsigned y; asm("cvt.rna.tf32.f32 %0, %1;" : "=r"(y) : "f"(x)); return y;
}
__device__ __forceinline__ void mma_tf32(float c[4], const unsigned a[4], const unsigned b[2]) {
    asm volatile("mma.sync.aligned.m16n8k8.row.col.f32.tf32.tf32.f32 "
        "{%0,%1,%2,%3},{%4,%5,%6,%7},{%8,%9},{%0,%1,%2,%3};\n"
        : "+f"(c[0]), "+f"(c[1]), "+f"(c[2]), "+f"(c[3])
        : "r"(a[0]), "r"(a[1]), "r"(a[2]), "r"(a[3]), "r"(b[0]), "r"(b[1]));
}

// ---------------------------------------------------------------------------
// gate[token] = sigmoid(dot(x[token,:], router_w) + router_b); one warp/token
// ---------------------------------------------------------------------------
__global__ __launch_bounds__(256) void gate_kernel(
    const float* __restrict__ x, const float* __restrict__ rw,
    const float* __restrict__ rb, float* __restrict__ gate)
{
    int warp = threadIdx.x >> 5, lane = threadIdx.x & 31;
    int token = blockIdx.x * 8 + warp;
    const float* xr = x + (size_t)token * Cq;
    float s = 0.f;
    #pragma unroll 8
    for (int i = lane; i < Cq; i += 32) s += xr[i] * rw[i];
    #pragma unroll
    for (int o = 16; o; o >>= 1) s += __shfl_xor_sync(0xffffffffu, s, o);
    if (lane == 0) {
        float z = s + rb[0];
        gate[token] = 1.f / (1.f + expf(-z));
    }
}

// ---------------------------------------------------------------------------
// per-batch bitonic sort (descending); threshold = s[KKEEP-1]
// ---------------------------------------------------------------------------
__global__ __launch_bounds__(1024) void topk_kernel(
    const float* __restrict__ gate, float* __restrict__ thr)
{
    __shared__ float s[2048];
    int b = blockIdx.x, t = threadIdx.x;
    s[t]        = gate[b * Nq + t];
    s[t + 1024] = gate[b * Nq + t + 1024];
    __syncthreads();
    for (int k2 = 2; k2 <= 2048; k2 <<= 1) {
        for (int j = k2 >> 1; j > 0; j >>= 1) {
            #pragma unroll
            for (int rep = 0; rep < 2; rep++) {
                int i = t + rep * 1024;
                int ixj = i ^ j;
                if (ixj > i) {
                    bool desc = ((i & k2) == 0);
                    float a = s[i], c = s[ixj];
                    if (desc ? (a < c) : (a > c)) { s[i] = c; s[ixj] = a; }
                }
            }
            __syncthreads();
        }
    }
    if (t == 0) thr[b] = s[KKEEP - 1];
}

// ---------------------------------------------------------------------------
// xg = x * gate * (gate >= thresh[b])
// ---------------------------------------------------------------------------
__global__ __launch_bounds__(256) void xg_kernel(
    const float4* __restrict__ x, const float* __restrict__ gate,
    const float* __restrict__ thr, float4* __restrict__ xg)
{
    int i = blockIdx.x * 256 + threadIdx.x;
    int token = i >> 8;
    int b = token >> 11;
    float g = gate[token];
    g = (g >= thr[b]) ? g : 0.f;
    float4 v = x[i];
    v.x *= g; v.y *= g; v.z *= g; v.w *= g;
    xg[i] = v;
}

// ---------------------------------------------------------------------------
// pack wq|wk|wv -> [1024,1536], bq|bk|bv -> [1536]
// ---------------------------------------------------------------------------
__global__ __launch_bounds__(256) void pack_kernel(
    const float* __restrict__ wq, const float* __restrict__ wk,
    const float* __restrict__ wv, const float* __restrict__ bq,
    const float* __restrict__ bk, const float* __restrict__ bv,
    float* __restrict__ wqkv, float* __restrict__ bqkv)
{
    int idx = blockIdx.x * 256 + threadIdx.x;   // 1024*384 float4
    int r = idx / 384, c4 = (idx % 384) * 4;
    float4 v;
    if (c4 < 1024)       v = *(const float4*)(wq + (size_t)r * 1024 + c4);
    else if (c4 < 1280)  v = *(const float4*)(wk + (size_t)r * 256 + (c4 - 1024));
    else                 v = *(const float4*)(wv + (size_t)r * 256 + (c4 - 1280));
    *(float4*)(wqkv + (size_t)r * 1536 + c4) = v;
    if (idx < 1536) {
        float bb;
        if (idx < 1024)      bb = bq[idx];
        else if (idx < 1280) bb = bk[idx - 1024];
        else                 bb = bv[idx - 1280];
        bqkv[idx] = bb;
    }
}

// ---------------------------------------------------------------------------
// TF32 GEMM: C[M,N] = A[M,K] @ B[K,N] + bias[N]
// 128x128 tile, Ktile=16, double-buffered cp.async, 8 warps (32x64 each)
// As[m][k] pitch 20 (bank: 20r+c bijective mod 32), Bs[k][n] pitch 136 (8c+r)
// ---------------------------------------------------------------------------
__global__ __launch_bounds__(256) void gemm_tf32(
    const float* __restrict__ A, const float* __restrict__ B,
    const float* __restrict__ bias, float* __restrict__ C,
    int M, int N, int K)
{
    __shared__ float As[2][128][20];
    __shared__ float Bs[2][16][136];
    const int t = threadIdx.x;
    const int warp = t >> 5, lane = t & 31;
    const int r = lane >> 2, c = lane & 3;
    const int wm = (warp & 3) * 32;
    const int wn = (warp >> 2) * 64;
    const int bm = blockIdx.y, bn = blockIdx.x;

    // loaders: A: elem e = t, t+256 -> row = (t>>2)+64l, k4 = (t&3)*4
    const int ar = t >> 2, ak4 = (t & 3) * 4;
    const float* Ag = A + (size_t)(bm * 128 + ar) * K + ak4;
    // B: elem e = t, t+256 -> row = (t>>5)+8l, n4 = (t&31)*4
    const int br = t >> 5, bn4 = (t & 31) * 4;
    const float* Bg = B + (size_t)br * N + bn * 128 + bn4;

    // preload tile 0
    cp_async16(&As[0][ar][ak4],      Ag);
    cp_async16(&As[0][ar + 64][ak4], Ag + (size_t)64 * K);
    cp_async16(&Bs[0][br][bn4],      Bg);
    cp_async16(&Bs[0][br + 8][bn4],  Bg + (size_t)8 * N);
    CP_COMMIT; CP_WAIT0;
    __syncthreads();

    float acc[2][8][4];
    #pragma unroll
    for (int mt = 0; mt < 2; mt++)
        #pragma unroll
        for (int nt = 0; nt < 8; nt++)
            #pragma unroll
            for (int i = 0; i < 4; i++) acc[mt][nt][i] = 0.f;

    const int nkt = K / 16;
    for (int kt = 0; kt < nkt; kt++) {
        const int cur = kt & 1, nxt = cur ^ 1;
        if (kt + 1 < nkt) {
            const float* Ag2 = Ag + (kt + 1) * 16;
            const float* Bg2 = Bg + (size_t)(kt + 1) * 16 * N;
            cp_async16(&As[nxt][ar][ak4],      Ag2);
            cp_async16(&As[nxt][ar + 64][ak4], Ag2 + (size_t)64 * K);
            cp_async16(&Bs[nxt][br][bn4],      Bg2);
            cp_async16(&Bs[nxt][br + 8][bn4],  Bg2 + (size_t)8 * N);
            CP_COMMIT;
        }
        #pragma unroll
        for (int ks = 0; ks < 16; ks += 8) {
            unsigned af[2][4];
            #pragma unroll
            for (int mt = 0; mt < 2; mt++) {
                int m0 = wm + mt * 16;
                af[mt][0] = f2tf(As[cur][m0 + r][ks + c]);
                af[mt][1] = f2tf(As[cur][m0 + r + 8][ks + c]);
                af[mt][2] = f2tf(As[cur][m0 + r][ks + c + 4]);
                af[mt][3] = f2tf(As[cur][m0 + r + 8][ks + c + 4]);
            }
            #pragma unroll
            for (int nt = 0; nt < 8; nt++) {
                unsigned bf[2];
                bf[0] = f2tf(Bs[cur][ks + c][wn + nt * 8 + r]);
                bf[1] = f2tf(Bs[cur][ks + c + 4][wn + nt * 8 + r]);
                mma_tf32(acc[0][nt], af[0], bf);
                mma_tf32(acc[1][nt], af[1], bf);
            }
        }
        if (kt + 1 < nkt) CP_WAIT0;
        __syncthreads();
    }

    // epilogue
    #pragma unroll
    for (int mt = 0; mt < 2; mt++) {
        int row0 = bm * 128 + wm + mt * 16 + r;
        #pragma unroll
        for (int nt = 0; nt < 8; nt++) {
            int col = bn * 128 + wn + nt * 8 + 2 * c;
            float b0 = __ldg(bias + col), b1 = __ldg(bias + col + 1);
            *(float2*)&C[(size_t)row0 * N + col] =
                make_float2(acc[mt][nt][0] + b0, acc[mt][nt][1] + b1);
            *(float2*)&C[(size_t)(row0 + 8) * N + col] =
                make_float2(acc[mt][nt][2] + b0, acc[mt][nt][3] + b1);
        }
    }
}

// ---------------------------------------------------------------------------
// TF32 flash attention: CTA = 128 q-rows x 1 head, 8 warps (16 rows each).
// Q in registers (A-frags), K/V double-buffered cp.async, 64-col K tiles.
// P round-trips through per-warp-private smem slice (syncwarp only).
// smem pitches: Ks 68 (4r+c), Vs 72 (8c+r), Ps 68 (4r+c) -- conflict-free.
// ---------------------------------------------------------------------------
#define AT_PK 68
#define AT_PV 72
#define AT_PP 68
#define KS_OFF 0
#define VS_OFF (2 * 64 * AT_PK)
#define PS_OFF (VS_OFF + 2 * 64 * AT_PV)
#define ATTN_SMEM ((PS_OFF + 128 * AT_PP) * 4)

__global__ __launch_bounds__(256, 2) void attn3(
    const float* __restrict__ QKV, float* __restrict__ O)
{
    extern __shared__ float sm[];
    const int t = threadIdx.x;
    const int warp = t >> 5, lane = t & 31;
    const int r = lane >> 2, c = lane & 3;
    const int wr = warp * 16;
    const int qt = blockIdx.x, h = blockIdx.y, b = blockIdx.z;
    const int hkv = h >> 2;

    const float* qp = QKV + (size_t)(b * Nq + qt * 128 + wr) * 1536 + h * 64;
    const float* kg = QKV + (size_t)b * Nq * 1536 + 1024 + hkv * 64;
    const float* vg = kg + 256;
    const float QSC = 0.125f * LOG2E;

    // Q fragments in registers (16 rows x 64 d per warp, 8 k-steps)
    unsigned qf[8][4];
    #pragma unroll
    for (int kc = 0; kc < 8; kc++) {
        qf[kc][0] = f2tf(qp[(size_t)r * 1536 + kc * 8 + c] * QSC);
        qf[kc][1] = f2tf(qp[(size_t)(r + 8) * 1536 + kc * 8 + c] * QSC);
        qf[kc][2] = f2tf(qp[(size_t)r * 1536 + kc * 8 + c + 4] * QSC);
        qf[kc][3] = f2tf(qp[(size_t)(r + 8) * 1536 + kc * 8 + c + 4] * QSC);
    }

    // K/V tile loaders: thread handles rows (t>>4)+16l, cols (t&15)*4
    const int lr = t >> 4, ld4 = (t & 15) * 4;

    // preload tile 0
    #pragma unroll
    for (int l = 0; l < 4; l++) {
        cp_async16(&sm[KS_OFF + (lr + 16 * l) * AT_PK + ld4],
                   kg + (size_t)(lr + 16 * l) * 1536 + ld4);
        cp_async16(&sm[VS_OFF + (lr + 16 * l) * AT_PV + ld4],
                   vg + (size_t)(lr + 16 * l) * 1536 + ld4);
    }
    CP_COMMIT; CP_WAIT0;

    float of[8][4];
    #pragma unroll
    for (int nt = 0; nt < 8; nt++)
        #pragma unroll
        for (int i = 0; i < 4; i++) of[nt][i] = 0.f;
    float m0 = -1e30f, m1 = -1e30f, l0 = 0.f, l1 = 0.f;

    __syncthreads();

    for (int kt = 0; kt < 32; kt++) {
        const int cur = kt & 1, nxt = cur ^ 1;
        const float* Kc = sm + KS_OFF + cur * 64 * AT_PK;
        const float* Vc = sm + VS_OFF + cur * 64 * AT_PV;

        // prefetch next K/V tile
        if (kt + 1 < 32) {
            float* Kn = sm + KS_OFF + nxt * 64 * AT_PK;
            float* Vn = sm + VS_OFF + nxt * 64 * AT_PV;
            #pragma unroll
            for (int l = 0; l < 4; l++) {
                int row = (kt + 1) * 64 + lr + 16 * l;
                cp_async16(&Kn[(lr + 16 * l) * AT_PK + ld4], kg + (size_t)row * 1536 + ld4);
                cp_async16(&Vn[(lr + 16 * l) * AT_PV + ld4], vg + (size_t)row * 1536 + ld4);
            }
            CP_COMMIT;
        }

        // S = Q K^T (log2 domain)
        float sf[8][4];
        #pragma unroll
        for (int nt = 0; nt < 8; nt++)
            #pragma unroll
            for (int i = 0; i < 4; i++) sf[nt][i] = 0.f;
        #pragma unroll
        for (int kc = 0; kc < 8; kc++) {
            #pragma unroll
            for (int nt = 0; nt < 8; nt++) {
                unsigned bf[2];
                bf[0] = f2tf(Kc[(nt * 8 + r) * AT_PK + kc * 8 + c]);
                bf[1] = f2tf(Kc[(nt * 8 + r) * AT_PK + kc * 8 + c + 4]);
                mma_tf32(sf[nt], qf[kc], bf);
            }
        }

        // online softmax in registers (rows r and r+8; quad = lanes xor 1,2)
        float mx0 = -1e30f, mx1 = -1e30f;
        #pragma unroll
        for (int nt = 0; nt < 8; nt++) {
            mx0 = fmaxf(mx0, fmaxf(sf[nt][0], sf[nt][1]));
            mx1 = fmaxf(mx1, fmaxf(sf[nt][2], sf[nt][3]));
        }
        mx0 = fmaxf(mx0, __shfl_xor_sync(0xffffffffu, mx0, 1));
        mx0 = fmaxf(mx0, __shfl_xor_sync(0xffffffffu, mx0, 2));
        mx1 = fmaxf(mx1, __shfl_xor_sync(0xffffffffu, mx1, 1));
        mx1 = fmaxf(mx1, __shfl_xor_sync(0xffffffffu, mx1, 2));
        float mn0 = fmaxf(m0, mx0), mn1 = fmaxf(m1, mx1);
        float sc0 = ex2(m0 - mn0), sc1 = ex2(m1 - mn1);
        float su0 = 0.f, su1 = 0.f;
        #pragma unroll
        for (int nt = 0; nt < 8; nt++) {
            sf[nt][0] = ex2(sf[nt][0] - mn0);
            sf[nt][1] = ex2(sf[nt][1] - mn0);
            sf[nt][2] = ex2(sf[nt][2] - mn1);
            sf[nt][3] = ex2(sf[nt][3] - mn1);
            su0 += sf[nt][0] + sf[nt][1];
            su1 += sf[nt][2] + sf[nt][3];
        }
        su0 += __shfl_xor_sync(0xffffffffu, su0, 1);
        su0 += __shfl_xor_sync(0xffffffffu, su0, 2);
        su1 += __shfl_xor_sync(0xffffffffu, su1, 1);
        su1 += __shfl_xor_sync(0xffffffffu, su1, 2);
        l0 = l0 * sc0 + su0; l1 = l1 * sc1 + su1;
        m0 = mn0; m1 = mn1;
        #pragma unroll
        for (int nt = 0; nt < 8; nt++) {
            of[nt][0] *= sc0; of[nt][1] *= sc0;
            of[nt][2] *= sc1; of[nt][3] *= sc1;
        }

        // P -> per-warp smem slice
        float* Ps = sm + PS_OFF;
        #pragma unroll
        for (int nt = 0; nt < 8; nt++) {
            *(float2*)&Ps[(wr + r) * AT_PP + nt * 8 + 2 * c] =
                make_float2(sf[nt][0], sf[nt][1]);
            *(float2*)&Ps[(wr + r + 8) * AT_PP + nt * 8 + 2 * c] =
                make_float2(sf[nt][2], sf[nt][3]);
        }
        __syncwarp();

        // O += P V
        #pragma unroll
        for (int kc = 0; kc < 8; kc++) {
            unsigned pf[4];
            pf[0] = f2tf(Ps[(wr + r) * AT_PP + kc * 8 + c]);
            pf[1] = f2tf(Ps[(wr + r + 8) * AT_PP + kc * 8 + c]);
            pf[2] = f2tf(Ps[(wr + r) * AT_PP + kc * 8 + c + 4]);
            pf[3] = f2tf(Ps[(wr + r + 8) * AT_PP + kc * 8 + c + 4]);
            #pragma unroll
            for (int nt = 0; nt < 8; nt++) {
                unsigned bf[2];
                bf[0] = f2tf(Vc[(kc * 8 + c) * AT_PV + nt * 8 + r]);
                bf[1] = f2tf(Vc[(kc * 8 + c + 4) * AT_PV + nt * 8 + r]);
                mma_tf32(of[nt], pf, bf);
            }
        }
        if (kt + 1 < 32) CP_WAIT0;
        __syncthreads();
    }

    // epilogue
    float inv0 = 1.f / l0, inv1 = 1.f / l1;
    size_t row0 = (size_t)(b * Nq + qt * 128 + wr + r);
    #pragma unroll
    for (int nt = 0; nt < 8; nt++) {
        int col = h * 64 + nt * 8 + 2 * c;
        *(float2*)&O[row0 * Cq + col] =
            make_float2(of[nt][0] * inv0, of[nt][1] * inv0);
        *(float2*)&O[(row0 + 8) * Cq + col] =
            make_float2(of[nt][2] * inv1, of[nt][3] * inv1);
    }
}

// ---------------------------------------------------------------------------
extern "C" void kernel_launch(void* const* d_in, const int* in_sizes, int n_in,
                              void* d_out, int out_size)
{
    const float* x   = (const float*)d_in[0];
    const float* rw  = (const float*)d_in[1];
    const float* rb  = (const float*)d_in[2];
    const float* wq  = (const float*)d_in[3];
    const float* bq  = (const float*)d_in[4];
    const float* wk  = (const float*)d_in[5];
    const float* bk  = (const float*)d_in[6];
    const float* wv  = (const float*)d_in[7];
    const float* bv  = (const float*)d_in[8];
    const float* wo  = (const float*)d_in[9];
    const float* bo  = (const float*)d_in[10];
    float* out = (float*)d_out;

    float* base;
    cudaGetSymbolAddress((void**)&base, g_scratch);
    float* xg   = base + XG_OFF;
    float* qkv  = base + QKV_OFF;
    float* ob   = base + OB_OFF;
    float* wqkv = base + WQKV_OFF;
    float* bqkv = base + BQKV_OFF;
    float* gate = base + GATE_OFF;
    float* thr  = base + THR_OFF;

    cudaFuncSetAttribute(attn3, cudaFuncAttributeMaxDynamicSharedMemorySize, ATTN_SMEM);

    gate_kernel<<<TOK / 8, 256>>>(x, rw, rb, gate);
    topk_kernel<<<Bq, 1024>>>(gate, thr);
    xg_kernel<<<(TOK * Cq) / (4 * 256), 256>>>((const float4*)x, gate, thr, (float4*)xg);
    pack_kernel<<<(1024 * 384) / 256, 256>>>(wq, wk, wv, bq, bk, bv, wqkv, bqkv);

    // fused QKV projection: [8192,1024] @ [1024,1536]
    gemm_tf32<<<dim3(1536 / 128, TOK / 128), 256>>>(xg, wqkv, bqkv, qkv, TOK, 1536, Cq);

    attn3<<<dim3(Nq / 128, Hq, Bq), 256, ATTN_SMEM>>>(qkv, ob);

    // output projection
    gemm_tf32<<<dim3(Cq / 128, TOK / 128), 256>>>(ob, wo, bo, out, TOK, Cq, Cq);
}

// round 5
// speedup vs baseline: 3.6614x; 1.1901x over previous
#include <cuda_runtime.h>
#include <cuda_bf16.h>
#include <math.h>

// ---------------------------------------------------------------------------
// MIGAttention: gate -> top-k mask -> GQA attention -> output projection
// B=4, N=2048, C=1024, H=16, HKV=4, DH=64, KEEP=0.7 -> k_keep=1433
// All matmuls on tensor cores, tf32 m16n8k8. All operands pre-rounded to
// tf32 (cvt.rna) at the source so inner loops are pure LDS + HMMA.
// ---------------------------------------------------------------------------

#define Bq 4
#define Nq 2048
#define Cq 1024
#define Hq 16
#define HKVq 4
#define DHq 64
#define TOK (Bq*Nq)          // 8192
#define KKEEP 1433
#define LOG2E 1.4426950408889634f

// scratch layout (floats)
#define XG_OFF   0u
#define QKV_OFF  8388608u                   // 8192*1536 = 12582912
#define OB_OFF   (QKV_OFF + 12582912u)      // 8192*1024 = 8388608
#define WQKV_OFF (OB_OFF + 8388608u)        // 1024*1536 = 1572864
#define WO_OFF   (WQKV_OFF + 1572864u)      // 1024*1024 = 1048576
#define BQKV_OFF (WO_OFF + 1048576u)        // 1536
#define GATE_OFF (BQKV_OFF + 1536u)         // 8192
#define THR_OFF  (GATE_OFF + 8192u)         // 4
#define SCRATCH_FLOATS (THR_OFF + 4u)
__device__ __align__(256) float g_scratch[SCRATCH_FLOATS];

__device__ __forceinline__ void cp_async16(void* smem, const void* gmem) {
    unsigned s = (unsigned)__cvta_generic_to_shared(smem);
    asm volatile("cp.async.cg.shared.global [%0], [%1], 16;\n" :: "r"(s), "l"(gmem));
}
#define CP_COMMIT asm volatile("cp.async.commit_group;\n" ::: "memory")
#define CP_WAIT0  asm volatile("cp.async.wait_group 0;\n" ::: "memory")

__device__ __forceinline__ float ex2(float x) {
    float y; asm("ex2.approx.f32 %0, %1;" : "=f"(y) : "f"(x)); return y;
}
// round fp32 -> tf32 bit pattern (rna)
__device__ __forceinline__ unsigned f2tf(float x) {
    unsigned y; asm("cvt.rna.tf32.f32 %0, %1;" : "=r"(y) : "f"(x)); return y;
}
__device__ __forceinline__ float rnd_tf(float x) { return __uint_as_float(f2tf(x)); }
__device__ __forceinline__ void mma_tf32(float c[4], const unsigned a[4], const unsigned b[2]) {
    asm volatile("mma.sync.aligned.m16n8k8.row.col.f32.tf32.tf32.f32 "
        "{%0,%1,%2,%3},{%4,%5,%6,%7},{%8,%9},{%0,%1,%2,%3};\n"
        : "+f"(c[0]), "+f"(c[1]), "+f"(c[2]), "+f"(c[3])
        : "r"(a[0]), "r"(a[1]), "r"(a[2]), "r"(a[3]), "r"(b[0]), "r"(b[1]));
}

// ---------------------------------------------------------------------------
// gate[token] = sigmoid(dot(x[token,:], router_w) + router_b); one warp/token
// ---------------------------------------------------------------------------
__global__ __launch_bounds__(256) void gate_kernel(
    const float* __restrict__ x, const float* __restrict__ rw,
    const float* __restrict__ rb, float* __restrict__ gate)
{
    int warp = threadIdx.x >> 5, lane = threadIdx.x & 31;
    int token = blockIdx.x * 8 + warp;
    const float* xr = x + (size_t)token * Cq;
    float s = 0.f;
    #pragma unroll 8
    for (int i = lane; i < Cq; i += 32) s += xr[i] * rw[i];
    #pragma unroll
    for (int o = 16; o; o >>= 1) s += __shfl_xor_sync(0xffffffffu, s, o);
    if (lane == 0) {
        float z = s + rb[0];
        gate[token] = 1.f / (1.f + expf(-z));
    }
}

// ---------------------------------------------------------------------------
// per-batch bitonic sort (descending); threshold = s[KKEEP-1]
// ---------------------------------------------------------------------------
__global__ __launch_bounds__(1024) void topk_kernel(
    const float* __restrict__ gate, float* __restrict__ thr)
{
    __shared__ float s[2048];
    int b = blockIdx.x, t = threadIdx.x;
    s[t]        = gate[b * Nq + t];
    s[t + 1024] = gate[b * Nq + t + 1024];
    __syncthreads();
    for (int k2 = 2; k2 <= 2048; k2 <<= 1) {
        for (int j = k2 >> 1; j > 0; j >>= 1) {
            #pragma unroll
            for (int rep = 0; rep < 2; rep++) {
                int i = t + rep * 1024;
                int ixj = i ^ j;
                if (ixj > i) {
                    bool desc = ((i & k2) == 0);
                    float a = s[i], c = s[ixj];
                    if (desc ? (a < c) : (a > c)) { s[i] = c; s[ixj] = a; }
                }
            }
            __syncthreads();
        }
    }
    if (t == 0) thr[b] = s[KKEEP - 1];
}

// ---------------------------------------------------------------------------
// xg = round_tf32( x * gate * (gate >= thresh[b]) )
// ---------------------------------------------------------------------------
__global__ __launch_bounds__(256) void xg_kernel(
    const float4* __restrict__ x, const float* __restrict__ gate,
    const float* __restrict__ thr, float4* __restrict__ xg)
{
    int i = blockIdx.x * 256 + threadIdx.x;
    int token = i >> 8;
    int b = token >> 11;
    float g = gate[token];
    g = (g >= thr[b]) ? g : 0.f;
    float4 v = x[i];
    v.x = rnd_tf(v.x * g); v.y = rnd_tf(v.y * g);
    v.z = rnd_tf(v.z * g); v.w = rnd_tf(v.w * g);
    xg[i] = v;
}

// ---------------------------------------------------------------------------
// pack wq|wk|wv -> [1024,1536] (tf32-rounded), bq|bk|bv -> [1536]
// ---------------------------------------------------------------------------
__global__ __launch_bounds__(256) void pack_kernel(
    const float* __restrict__ wq, const float* __restrict__ wk,
    const float* __restrict__ wv, const float* __restrict__ bq,
    const float* __restrict__ bk, const float* __restrict__ bv,
    float* __restrict__ wqkv, float* __restrict__ bqkv)
{
    int idx = blockIdx.x * 256 + threadIdx.x;   // 1024*384 float4
    int r = idx / 384, c4 = (idx % 384) * 4;
    float4 v;
    if (c4 < 1024)       v = *(const float4*)(wq + (size_t)r * 1024 + c4);
    else if (c4 < 1280)  v = *(const float4*)(wk + (size_t)r * 256 + (c4 - 1024));
    else                 v = *(const float4*)(wv + (size_t)r * 256 + (c4 - 1280));
    v.x = rnd_tf(v.x); v.y = rnd_tf(v.y); v.z = rnd_tf(v.z); v.w = rnd_tf(v.w);
    *(float4*)(wqkv + (size_t)r * 1536 + c4) = v;
    if (idx < 1536) {
        float bb;
        if (idx < 1024)      bb = bq[idx];
        else if (idx < 1280) bb = bk[idx - 1024];
        else                 bb = bv[idx - 1280];
        bqkv[idx] = bb;
    }
}

// round a weight matrix to tf32 (float4 elementwise)
__global__ __launch_bounds__(256) void round_kernel(
    const float4* __restrict__ src, float4* __restrict__ dst)
{
    int i = blockIdx.x * 256 + threadIdx.x;
    float4 v = src[i];
    v.x = rnd_tf(v.x); v.y = rnd_tf(v.y); v.z = rnd_tf(v.z); v.w = rnd_tf(v.w);
    dst[i] = v;
}

// ---------------------------------------------------------------------------
// TF32 GEMM: C[M,N] = A[M,K] @ B[K,N] + bias[N]; inputs pre-rounded to tf32.
// 128x128 tile, Ktile=16, double-buffered cp.async, 8 warps (32x64 each).
// RND: round output to tf32 (for intermediate buffers feeding later mma).
// ---------------------------------------------------------------------------
template<bool RND>
__global__ __launch_bounds__(256) void gemm_tf32(
    const float* __restrict__ A, const float* __restrict__ B,
    const float* __restrict__ bias, float* __restrict__ C,
    int M, int N, int K)
{
    __shared__ float As[2][128][20];
    __shared__ float Bs[2][16][136];
    const int t = threadIdx.x;
    const int warp = t >> 5, lane = t & 31;
    const int r = lane >> 2, c = lane & 3;
    const int wm = (warp & 3) * 32;
    const int wn = (warp >> 2) * 64;
    const int bm = blockIdx.y, bn = blockIdx.x;

    const int ar = t >> 2, ak4 = (t & 3) * 4;
    const float* Ag = A + (size_t)(bm * 128 + ar) * K + ak4;
    const int br = t >> 5, bn4 = (t & 31) * 4;
    const float* Bg = B + (size_t)br * N + bn * 128 + bn4;

    cp_async16(&As[0][ar][ak4],      Ag);
    cp_async16(&As[0][ar + 64][ak4], Ag + (size_t)64 * K);
    cp_async16(&Bs[0][br][bn4],      Bg);
    cp_async16(&Bs[0][br + 8][bn4],  Bg + (size_t)8 * N);
    CP_COMMIT; CP_WAIT0;
    __syncthreads();

    float acc[2][8][4];
    #pragma unroll
    for (int mt = 0; mt < 2; mt++)
        #pragma unroll
        for (int nt = 0; nt < 8; nt++)
            #pragma unroll
            for (int i = 0; i < 4; i++) acc[mt][nt][i] = 0.f;

    const int nkt = K / 16;
    for (int kt = 0; kt < nkt; kt++) {
        const int cur = kt & 1, nxt = cur ^ 1;
        if (kt + 1 < nkt) {
            const float* Ag2 = Ag + (kt + 1) * 16;
            const float* Bg2 = Bg + (size_t)(kt + 1) * 16 * N;
            cp_async16(&As[nxt][ar][ak4],      Ag2);
            cp_async16(&As[nxt][ar + 64][ak4], Ag2 + (size_t)64 * K);
            cp_async16(&Bs[nxt][br][bn4],      Bg2);
            cp_async16(&Bs[nxt][br + 8][bn4],  Bg2 + (size_t)8 * N);
            CP_COMMIT;
        }
        #pragma unroll
        for (int ks = 0; ks < 16; ks += 8) {
            unsigned af[2][4];
            #pragma unroll
            for (int mt = 0; mt < 2; mt++) {
                int m0 = wm + mt * 16;
                af[mt][0] = __float_as_uint(As[cur][m0 + r][ks + c]);
                af[mt][1] = __float_as_uint(As[cur][m0 + r + 8][ks + c]);
                af[mt][2] = __float_as_uint(As[cur][m0 + r][ks + c + 4]);
                af[mt][3] = __float_as_uint(As[cur][m0 + r + 8][ks + c + 4]);
            }
            #pragma unroll
            for (int nt = 0; nt < 8; nt++) {
                unsigned bf[2];
                bf[0] = __float_as_uint(Bs[cur][ks + c][wn + nt * 8 + r]);
                bf[1] = __float_as_uint(Bs[cur][ks + c + 4][wn + nt * 8 + r]);
                mma_tf32(acc[0][nt], af[0], bf);
                mma_tf32(acc[1][nt], af[1], bf);
            }
        }
        if (kt + 1 < nkt) CP_WAIT0;
        __syncthreads();
    }

    #pragma unroll
    for (int mt = 0; mt < 2; mt++) {
        int row0 = bm * 128 + wm + mt * 16 + r;
        #pragma unroll
        for (int nt = 0; nt < 8; nt++) {
            int col = bn * 128 + wn + nt * 8 + 2 * c;
            float b0 = __ldg(bias + col), b1 = __ldg(bias + col + 1);
            float v00 = acc[mt][nt][0] + b0, v01 = acc[mt][nt][1] + b1;
            float v10 = acc[mt][nt][2] + b0, v11 = acc[mt][nt][3] + b1;
            if (RND) { v00 = rnd_tf(v00); v01 = rnd_tf(v01);
                       v10 = rnd_tf(v10); v11 = rnd_tf(v11); }
            *(float2*)&C[(size_t)row0 * N + col]       = make_float2(v00, v01);
            *(float2*)&C[(size_t)(row0 + 8) * N + col] = make_float2(v10, v11);
        }
    }
}

// ---------------------------------------------------------------------------
// TF32 flash attention: CTA = 128 q-rows x 1 head, 8 warps (16 rows each).
// Q in registers (A-frags), K/V double-buffered cp.async, 64-col K tiles.
// K/V pre-rounded tf32 (no cvt); P re-rounded via f2tf (32 cvt/tile).
// ---------------------------------------------------------------------------
#define AT_PK 68
#define AT_PV 72
#define AT_PP 68
#define KS_OFF 0
#define VS_OFF (2 * 64 * AT_PK)
#define PS_OFF (VS_OFF + 2 * 64 * AT_PV)
#define ATTN_SMEM ((PS_OFF + 128 * AT_PP) * 4)

__global__ __launch_bounds__(256, 2) void attn3(
    const float* __restrict__ QKV, float* __restrict__ O)
{
    extern __shared__ float sm[];
    const int t = threadIdx.x;
    const int warp = t >> 5, lane = t & 31;
    const int r = lane >> 2, c = lane & 3;
    const int wr = warp * 16;
    const int qt = blockIdx.x, h = blockIdx.y, b = blockIdx.z;
    const int hkv = h >> 2;

    const float* qp = QKV + (size_t)(b * Nq + qt * 128 + wr) * 1536 + h * 64;
    const float* kg = QKV + (size_t)b * Nq * 1536 + 1024 + hkv * 64;
    const float* vg = kg + 256;
    const float QSC = 0.125f * LOG2E;

    unsigned qf[8][4];
    #pragma unroll
    for (int kc = 0; kc < 8; kc++) {
        qf[kc][0] = f2tf(qp[(size_t)r * 1536 + kc * 8 + c] * QSC);
        qf[kc][1] = f2tf(qp[(size_t)(r + 8) * 1536 + kc * 8 + c] * QSC);
        qf[kc][2] = f2tf(qp[(size_t)r * 1536 + kc * 8 + c + 4] * QSC);
        qf[kc][3] = f2tf(qp[(size_t)(r + 8) * 1536 + kc * 8 + c + 4] * QSC);
    }

    const int lr = t >> 4, ld4 = (t & 15) * 4;

    #pragma unroll
    for (int l = 0; l < 4; l++) {
        cp_async16(&sm[KS_OFF + (lr + 16 * l) * AT_PK + ld4],
                   kg + (size_t)(lr + 16 * l) * 1536 + ld4);
        cp_async16(&sm[VS_OFF + (lr + 16 * l) * AT_PV + ld4],
                   vg + (size_t)(lr + 16 * l) * 1536 + ld4);
    }
    CP_COMMIT; CP_WAIT0;

    float of[8][4];
    #pragma unroll
    for (int nt = 0; nt < 8; nt++)
        #pragma unroll
        for (int i = 0; i < 4; i++) of[nt][i] = 0.f;
    float m0 = -1e30f, m1 = -1e30f, l0 = 0.f, l1 = 0.f;

    __syncthreads();

    for (int kt = 0; kt < 32; kt++) {
        const int cur = kt & 1, nxt = cur ^ 1;
        const float* Kc = sm + KS_OFF + cur * 64 * AT_PK;
        const float* Vc = sm + VS_OFF + cur * 64 * AT_PV;

        if (kt + 1 < 32) {
            float* Kn = sm + KS_OFF + nxt * 64 * AT_PK;
            float* Vn = sm + VS_OFF + nxt * 64 * AT_PV;
            #pragma unroll
            for (int l = 0; l < 4; l++) {
                int row = (kt + 1) * 64 + lr + 16 * l;
                cp_async16(&Kn[(lr + 16 * l) * AT_PK + ld4], kg + (size_t)row * 1536 + ld4);
                cp_async16(&Vn[(lr + 16 * l) * AT_PV + ld4], vg + (size_t)row * 1536 + ld4);
            }
            CP_COMMIT;
        }

        // S = Q K^T (log2 domain)
        float sf[8][4];
        #pragma unroll
        for (int nt = 0; nt < 8; nt++)
            #pragma unroll
            for (int i = 0; i < 4; i++) sf[nt][i] = 0.f;
        #pragma unroll
        for (int kc = 0; kc < 8; kc++) {
            #pragma unroll
            for (int nt = 0; nt < 8; nt++) {
                unsigned bf[2];
                bf[0] = __float_as_uint(Kc[(nt * 8 + r) * AT_PK + kc * 8 + c]);
                bf[1] = __float_as_uint(Kc[(nt * 8 + r) * AT_PK + kc * 8 + c + 4]);
                mma_tf32(sf[nt], qf[kc], bf);
            }
        }

        // online softmax in registers
        float mx0 = -1e30f, mx1 = -1e30f;
        #pragma unroll
        for (int nt = 0; nt < 8; nt++) {
            mx0 = fmaxf(mx0, fmaxf(sf[nt][0], sf[nt][1]));
            mx1 = fmaxf(mx1, fmaxf(sf[nt][2], sf[nt][3]));
        }
        mx0 = fmaxf(mx0, __shfl_xor_sync(0xffffffffu, mx0, 1));
        mx0 = fmaxf(mx0, __shfl_xor_sync(0xffffffffu, mx0, 2));
        mx1 = fmaxf(mx1, __shfl_xor_sync(0xffffffffu, mx1, 1));
        mx1 = fmaxf(mx1, __shfl_xor_sync(0xffffffffu, mx1, 2));
        float mn0 = fmaxf(m0, mx0), mn1 = fmaxf(m1, mx1);
        float sc0 = ex2(m0 - mn0), sc1 = ex2(m1 - mn1);
        float su0 = 0.f, su1 = 0.f;
        #pragma unroll
        for (int nt = 0; nt < 8; nt++) {
            sf[nt][0] = ex2(sf[nt][0] - mn0);
            sf[nt][1] = ex2(sf[nt][1] - mn0);
            sf[nt][2] = ex2(sf[nt][2] - mn1);
            sf[nt][3] = ex2(sf[nt][3] - mn1);
            su0 += sf[nt][0] + sf[nt][1];
            su1 += sf[nt][2] + sf[nt][3];
        }
        su0 += __shfl_xor_sync(0xffffffffu, su0, 1);
        su0 += __shfl_xor_sync(0xffffffffu, su0, 2);
        su1 += __shfl_xor_sync(0xffffffffu, su1, 1);
        su1 += __shfl_xor_sync(0xffffffffu, su1, 2);
        l0 = l0 * sc0 + su0; l1 = l1 * sc1 + su1;
        m0 = mn0; m1 = mn1;
        #pragma unroll
        for (int nt = 0; nt < 8; nt++) {
            of[nt][0] *= sc0; of[nt][1] *= sc0;
            of[nt][2] *= sc1; of[nt][3] *= sc1;
        }

        // P -> per-warp smem slice
        float* Ps = sm + PS_OFF;
        #pragma unroll
        for (int nt = 0; nt < 8; nt++) {
            *(float2*)&Ps[(wr + r) * AT_PP + nt * 8 + 2 * c] =
                make_float2(sf[nt][0], sf[nt][1]);
            *(float2*)&Ps[(wr + r + 8) * AT_PP + nt * 8 + 2 * c] =
                make_float2(sf[nt][2], sf[nt][3]);
        }
        __syncwarp();

        // O += P V
        #pragma unroll
        for (int kc = 0; kc < 8; kc++) {
            unsigned pf[4];
            pf[0] = f2tf(Ps[(wr + r) * AT_PP + kc * 8 + c]);
            pf[1] = f2tf(Ps[(wr + r + 8) * AT_PP + kc * 8 + c]);
            pf[2] = f2tf(Ps[(wr + r) * AT_PP + kc * 8 + c + 4]);
            pf[3] = f2tf(Ps[(wr + r + 8) * AT_PP + kc * 8 + c + 4]);
            #pragma unroll
            for (int nt = 0; nt < 8; nt++) {
                unsigned bf[2];
                bf[0] = __float_as_uint(Vc[(kc * 8 + c) * AT_PV + nt * 8 + r]);
                bf[1] = __float_as_uint(Vc[(kc * 8 + c + 4) * AT_PV + nt * 8 + r]);
                mma_tf32(of[nt], pf, bf);
            }
        }
        if (kt + 1 < 32) CP_WAIT0;
        __syncthreads();
    }

    // epilogue: round O to tf32 (feeds out-proj GEMM)
    float inv0 = 1.f / l0, inv1 = 1.f / l1;
    size_t row0 = (size_t)(b * Nq + qt * 128 + wr + r);
    #pragma unroll
    for (int nt = 0; nt < 8; nt++) {
        int col = h * 64 + nt * 8 + 2 * c;
        *(float2*)&O[row0 * Cq + col] =
            make_float2(rnd_tf(of[nt][0] * inv0), rnd_tf(of[nt][1] * inv0));
        *(float2*)&O[(row0 + 8) * Cq + col] =
            make_float2(rnd_tf(of[nt][2] * inv1), rnd_tf(of[nt][3] * inv1));
    }
}

// ---------------------------------------------------------------------------
extern "C" void kernel_launch(void* const* d_in, const int* in_sizes, int n_in,
                              void* d_out, int out_size)
{
    const float* x   = (const float*)d_in[0];
    const float* rw  = (const float*)d_in[1];
    const float* rb  = (const float*)d_in[2];
    const float* wq  = (const float*)d_in[3];
    const float* bq  = (const float*)d_in[4];
    const float* wk  = (const float*)d_in[5];
    const float* bk  = (const float*)d_in[6];
    const float* wv  = (const float*)d_in[7];
    const float* bv  = (const float*)d_in[8];
    const float* wo  = (const float*)d_in[9];
    const float* bo  = (const float*)d_in[10];
    float* out = (float*)d_out;

    float* base;
    cudaGetSymbolAddress((void**)&base, g_scratch);
    float* xg   = base + XG_OFF;
    float* qkv  = base + QKV_OFF;
    float* ob   = base + OB_OFF;
    float* wqkv = base + WQKV_OFF;
    float* wor  = base + WO_OFF;
    float* bqkv = base + BQKV_OFF;
    float* gate = base + GATE_OFF;
    float* thr  = base + THR_OFF;

    cudaFuncSetAttribute(attn3, cudaFuncAttributeMaxDynamicSharedMemorySize, ATTN_SMEM);

    gate_kernel<<<TOK / 8, 256>>>(x, rw, rb, gate);
    topk_kernel<<<Bq, 1024>>>(gate, thr);
    xg_kernel<<<(TOK * Cq) / (4 * 256), 256>>>((const float4*)x, gate, thr, (float4*)xg);
    pack_kernel<<<(1024 * 384) / 256, 256>>>(wq, wk, wv, bq, bk, bv, wqkv, bqkv);
    round_kernel<<<(1024 * 256) / 256, 256>>>((const float4*)wo, (float4*)wor);

    // fused QKV projection (rounded output): [8192,1024] @ [1024,1536]
    gemm_tf32<true><<<dim3(1536 / 128, TOK / 128), 256>>>(xg, wqkv, bqkv, qkv, TOK, 1536, Cq);

    attn3<<<dim3(Nq / 128, Hq, Bq), 256, ATTN_SMEM>>>(qkv, ob);

    // output projection (fp32 output)
    gemm_tf32<false><<<dim3(Cq / 128, TOK / 128), 256>>>(ob, wor, bo, out, TOK, Cq, Cq);
}

// round 6
// speedup vs baseline: 3.7194x; 1.0159x over previous
#include <cuda_runtime.h>
#include <cuda_bf16.h>
#include <math.h>

// ---------------------------------------------------------------------------
// MIGAttention: gate -> top-k mask -> GQA attention -> output projection
// B=4, N=2048, C=1024, H=16, HKV=4, DH=64, KEEP=0.7 -> k_keep=1433
// tf32 mma everywhere; K/V stored in mma-fragment-friendly permuted layouts
// by the QKV GEMM epilogue so attention fragment loads are LDS.128.
// ---------------------------------------------------------------------------

#define Bq 4
#define Nq 2048
#define Cq 1024
#define Hq 16
#define HKVq 4
#define DHq 64
#define TOK (Bq*Nq)          // 8192
#define KKEEP 1433
#define LOG2E 1.4426950408889634f

// scratch layout (floats)
#define XG_OFF   0u
#define QB_OFF   8388608u                  // 8192*1024
#define KP_OFF   (QB_OFF + 8388608u)       // 16 * 131072 = 2097152
#define VP_OFF   (KP_OFF + 2097152u)       // 2097152
#define OB_OFF   (VP_OFF + 2097152u)       // 8388608
#define WQKV_OFF (OB_OFF + 8388608u)       // 1572864
#define WO_OFF   (WQKV_OFF + 1572864u)     // 1048576
#define BQKV_OFF (WO_OFF + 1048576u)       // 1536
#define GATE_OFF (BQKV_OFF + 1536u)        // 8192
#define THR_OFF  (GATE_OFF + 8192u)        // 4
#define SCRATCH_FLOATS (THR_OFF + 4u)
__device__ __align__(256) float g_scratch[SCRATCH_FLOATS];

__device__ __forceinline__ void cp_async16(void* smem, const void* gmem) {
    unsigned s = (unsigned)__cvta_generic_to_shared(smem);
    asm volatile("cp.async.cg.shared.global [%0], [%1], 16;\n" :: "r"(s), "l"(gmem));
}
#define CP_COMMIT asm volatile("cp.async.commit_group;\n" ::: "memory")
#define CP_WAIT0  asm volatile("cp.async.wait_group 0;\n" ::: "memory")
#define CP_WAIT1  asm volatile("cp.async.wait_group 1;\n" ::: "memory")
#define CP_WAIT2  asm volatile("cp.async.wait_group 2;\n" ::: "memory")

__device__ __forceinline__ float ex2(float x) {
    float y; asm("ex2.approx.f32 %0, %1;" : "=f"(y) : "f"(x)); return y;
}
__device__ __forceinline__ unsigned f2tf(float x) {
    unsigned y; asm("cvt.rna.tf32.f32 %0, %1;" : "=r"(y) : "f"(x)); return y;
}
__device__ __forceinline__ float rnd_tf(float x) { return __uint_as_float(f2tf(x)); }
__device__ __forceinline__ void mma_tf32(float c[4], const unsigned a[4], const unsigned b[2]) {
    asm volatile("mma.sync.aligned.m16n8k8.row.col.f32.tf32.tf32.f32 "
        "{%0,%1,%2,%3},{%4,%5,%6,%7},{%8,%9},{%0,%1,%2,%3};\n"
        : "+f"(c[0]), "+f"(c[1]), "+f"(c[2]), "+f"(c[3])
        : "r"(a[0]), "r"(a[1]), "r"(a[2]), "r"(a[3]), "r"(b[0]), "r"(b[1]));
}

// ---------------------------------------------------------------------------
__global__ __launch_bounds__(256) void gate_kernel(
    const float* __restrict__ x, const float* __restrict__ rw,
    const float* __restrict__ rb, float* __restrict__ gate)
{
    int warp = threadIdx.x >> 5, lane = threadIdx.x & 31;
    int token = blockIdx.x * 8 + warp;
    const float* xr = x + (size_t)token * Cq;
    float s = 0.f;
    #pragma unroll 8
    for (int i = lane; i < Cq; i += 32) s += xr[i] * rw[i];
    #pragma unroll
    for (int o = 16; o; o >>= 1) s += __shfl_xor_sync(0xffffffffu, s, o);
    if (lane == 0) {
        float z = s + rb[0];
        gate[token] = 1.f / (1.f + expf(-z));
    }
}

// ---------------------------------------------------------------------------
__global__ __launch_bounds__(1024) void topk_kernel(
    const float* __restrict__ gate, float* __restrict__ thr)
{
    __shared__ float s[2048];
    int b = blockIdx.x, t = threadIdx.x;
    s[t]        = gate[b * Nq + t];
    s[t + 1024] = gate[b * Nq + t + 1024];
    __syncthreads();
    for (int k2 = 2; k2 <= 2048; k2 <<= 1) {
        for (int j = k2 >> 1; j > 0; j >>= 1) {
            #pragma unroll
            for (int rep = 0; rep < 2; rep++) {
                int i = t + rep * 1024;
                int ixj = i ^ j;
                if (ixj > i) {
                    bool desc = ((i & k2) == 0);
                    float a = s[i], c = s[ixj];
                    if (desc ? (a < c) : (a > c)) { s[i] = c; s[ixj] = a; }
                }
            }
            __syncthreads();
        }
    }
    if (t == 0) thr[b] = s[KKEEP - 1];
}

// ---------------------------------------------------------------------------
__global__ __launch_bounds__(256) void xg_kernel(
    const float4* __restrict__ x, const float* __restrict__ gate,
    const float* __restrict__ thr, float4* __restrict__ xg)
{
    int i = blockIdx.x * 256 + threadIdx.x;
    int token = i >> 8;
    int b = token >> 11;
    float g = gate[token];
    g = (g >= thr[b]) ? g : 0.f;
    float4 v = x[i];
    v.x = rnd_tf(v.x * g); v.y = rnd_tf(v.y * g);
    v.z = rnd_tf(v.z * g); v.w = rnd_tf(v.w * g);
    xg[i] = v;
}

// ---------------------------------------------------------------------------
__global__ __launch_bounds__(256) void pack_kernel(
    const float* __restrict__ wq, const float* __restrict__ wk,
    const float* __restrict__ wv, const float* __restrict__ bq,
    const float* __restrict__ bk, const float* __restrict__ bv,
    float* __restrict__ wqkv, float* __restrict__ bqkv)
{
    int idx = blockIdx.x * 256 + threadIdx.x;
    int r = idx / 384, c4 = (idx % 384) * 4;
    float4 v;
    if (c4 < 1024)       v = *(const float4*)(wq + (size_t)r * 1024 + c4);
    else if (c4 < 1280)  v = *(const float4*)(wk + (size_t)r * 256 + (c4 - 1024));
    else                 v = *(const float4*)(wv + (size_t)r * 256 + (c4 - 1280));
    v.x = rnd_tf(v.x); v.y = rnd_tf(v.y); v.z = rnd_tf(v.z); v.w = rnd_tf(v.w);
    *(float4*)(wqkv + (size_t)r * 1536 + c4) = v;
    if (idx < 1536) {
        float bb;
        if (idx < 1024)      bb = bq[idx];
        else if (idx < 1280) bb = bk[idx - 1024];
        else                 bb = bv[idx - 1280];
        bqkv[idx] = bb;
    }
}

__global__ __launch_bounds__(256) void round_kernel(
    const float4* __restrict__ src, float4* __restrict__ dst)
{
    int i = blockIdx.x * 256 + threadIdx.x;
    float4 v = src[i];
    v.x = rnd_tf(v.x); v.y = rnd_tf(v.y); v.z = rnd_tf(v.z); v.w = rnd_tf(v.w);
    dst[i] = v;
}

// ---------------------------------------------------------------------------
// TF32 GEMM. MODE 0: C = A@B + bias, plain fp32 row-major out.
// MODE 1 (QKV): N=1536; bn<8 -> Q rows into Qb[token][1024] (tf32-rounded);
//   bn 8-9 -> K into Kp[(b*4+hkv)*4 + d%4][kv][d/4]; bn 10-11 -> V into
//   Vp[(b*4+hkv)*4 + kv%4][d][kv/4]. All rounded to tf32.
// ---------------------------------------------------------------------------
template<int MODE>
__global__ __launch_bounds__(256) void gemm_tf32(
    const float* __restrict__ A, const float* __restrict__ B,
    const float* __restrict__ bias, float* __restrict__ C,
    float* __restrict__ Kp, float* __restrict__ Vp,
    int M, int N, int K)
{
    __shared__ float As[2][128][20];
    __shared__ float Bs[2][16][136];
    const int t = threadIdx.x;
    const int warp = t >> 5, lane = t & 31;
    const int r = lane >> 2, c = lane & 3;
    const int wm = (warp & 3) * 32;
    const int wn = (warp >> 2) * 64;
    const int bm = blockIdx.y, bn = blockIdx.x;

    const int ar = t >> 2, ak4 = (t & 3) * 4;
    const float* Ag = A + (size_t)(bm * 128 + ar) * K + ak4;
    const int br = t >> 5, bn4 = (t & 31) * 4;
    const float* Bg = B + (size_t)br * N + bn * 128 + bn4;

    cp_async16(&As[0][ar][ak4],      Ag);
    cp_async16(&As[0][ar + 64][ak4], Ag + (size_t)64 * K);
    cp_async16(&Bs[0][br][bn4],      Bg);
    cp_async16(&Bs[0][br + 8][bn4],  Bg + (size_t)8 * N);
    CP_COMMIT; CP_WAIT0;
    __syncthreads();

    float acc[2][8][4];
    #pragma unroll
    for (int mt = 0; mt < 2; mt++)
        #pragma unroll
        for (int nt = 0; nt < 8; nt++)
            #pragma unroll
            for (int i = 0; i < 4; i++) acc[mt][nt][i] = 0.f;

    const int nkt = K / 16;
    for (int kt = 0; kt < nkt; kt++) {
        const int cur = kt & 1, nxt = cur ^ 1;
        if (kt + 1 < nkt) {
            const float* Ag2 = Ag + (kt + 1) * 16;
            const float* Bg2 = Bg + (size_t)(kt + 1) * 16 * N;
            cp_async16(&As[nxt][ar][ak4],      Ag2);
            cp_async16(&As[nxt][ar + 64][ak4], Ag2 + (size_t)64 * K);
            cp_async16(&Bs[nxt][br][bn4],      Bg2);
            cp_async16(&Bs[nxt][br + 8][bn4],  Bg2 + (size_t)8 * N);
            CP_COMMIT;
        }
        #pragma unroll
        for (int ks = 0; ks < 16; ks += 8) {
            unsigned af[2][4];
            #pragma unroll
            for (int mt = 0; mt < 2; mt++) {
                int m0 = wm + mt * 16;
                af[mt][0] = __float_as_uint(As[cur][m0 + r][ks + c]);
                af[mt][1] = __float_as_uint(As[cur][m0 + r + 8][ks + c]);
                af[mt][2] = __float_as_uint(As[cur][m0 + r][ks + c + 4]);
                af[mt][3] = __float_as_uint(As[cur][m0 + r + 8][ks + c + 4]);
            }
            #pragma unroll
            for (int nt = 0; nt < 8; nt++) {
                unsigned bf[2];
                bf[0] = __float_as_uint(Bs[cur][ks + c][wn + nt * 8 + r]);
                bf[1] = __float_as_uint(Bs[cur][ks + c + 4][wn + nt * 8 + r]);
                mma_tf32(acc[0][nt], af[0], bf);
                mma_tf32(acc[1][nt], af[1], bf);
            }
        }
        if (kt + 1 < nkt) CP_WAIT0;
        __syncthreads();
    }

    // epilogue
    #pragma unroll
    for (int mt = 0; mt < 2; mt++) {
        int row0 = bm * 128 + wm + mt * 16 + r;
        #pragma unroll
        for (int nt = 0; nt < 8; nt++) {
            int col = bn * 128 + wn + nt * 8 + 2 * c;
            float b0 = __ldg(bias + col), b1 = __ldg(bias + col + 1);
            float v00 = acc[mt][nt][0] + b0, v01 = acc[mt][nt][1] + b1;
            float v10 = acc[mt][nt][2] + b0, v11 = acc[mt][nt][3] + b1;
            if (MODE == 0) {
                *(float2*)&C[(size_t)row0 * N + col]       = make_float2(v00, v01);
                *(float2*)&C[(size_t)(row0 + 8) * N + col] = make_float2(v10, v11);
            } else {
                v00 = rnd_tf(v00); v01 = rnd_tf(v01);
                v10 = rnd_tf(v10); v11 = rnd_tf(v11);
                if (bn < 8) {
                    // Q: row-major [token][1024]
                    *(float2*)&C[(size_t)row0 * 1024 + col]       = make_float2(v00, v01);
                    *(float2*)&C[(size_t)(row0 + 8) * 1024 + col] = make_float2(v10, v11);
                } else if (bn < 10) {
                    // K -> Kp
                    int rel = col - 1024;
                    int hkv = rel >> 6;
                    #pragma unroll
                    for (int cc = 0; cc < 2; cc++) {
                        int d = (rel + cc) & 63;
                        float va = cc ? v01 : v00;
                        float vb = cc ? v11 : v10;
                        #pragma unroll
                        for (int rr = 0; rr < 2; rr++) {
                            int token = row0 + rr * 8;
                            int b = token >> 11, kv = token & 2047;
                            Kp[((size_t)((b * 4 + hkv) * 4 + (d & 3)) * 2048 + kv) * 16 + (d >> 2)]
                                = rr ? vb : va;
                        }
                    }
                } else {
                    // V -> Vp
                    int rel = col - 1280;
                    int hkv = rel >> 6;
                    #pragma unroll
                    for (int cc = 0; cc < 2; cc++) {
                        int d = (rel + cc) & 63;
                        float va = cc ? v01 : v00;
                        float vb = cc ? v11 : v10;
                        #pragma unroll
                        for (int rr = 0; rr < 2; rr++) {
                            int token = row0 + rr * 8;
                            int b = token >> 11, kv = token & 2047;
                            Vp[((size_t)((b * 4 + hkv) * 4 + (kv & 3)) * 64 + d) * 512 + (kv >> 2)]
                                = rr ? vb : va;
                        }
                    }
                }
            }
        }
    }
}

// ---------------------------------------------------------------------------
// TF32 flash attention v4: permuted K/V layouts -> LDS.128 fragment loads.
// CTA = 128 q-rows x 1 head, 8 warps. K double-buffered, V single-buffered.
// smem: Ks[2][4 planes][64 kv][20], Vs[4][64 d][20], Ps[128][68].
// plane stride 1288 (= 64*20 + 8) gives conflict-free LDS.128 phases.
// ---------------------------------------------------------------------------
#define PLANE_STRIDE 1288
#define KBUF (4 * PLANE_STRIDE)          // 5152 floats per K buffer
#define VS_OFF4 (2 * KBUF)               // V after 2 K buffers
#define PS_OFF4 (VS_OFF4 + KBUF)         // P after V
#define ATTN_SMEM ((PS_OFF4 + 128 * 68) * 4)

__global__ __launch_bounds__(256, 2) void attn4(
    const float* __restrict__ Qb, const float* __restrict__ Kpg,
    const float* __restrict__ Vpg, float* __restrict__ O)
{
    extern __shared__ float sm[];
    const int t = threadIdx.x;
    const int warp = t >> 5, lane = t & 31;
    const int r = lane >> 2, c = lane & 3;
    const int wr = warp * 16;
    const int qt = blockIdx.x, h = blockIdx.y, b = blockIdx.z;
    const int hkv = h >> 2;

    const float* qp = Qb + (size_t)(b * Nq + qt * 128 + wr) * Cq + h * 64;
    const float* Kg = Kpg + (size_t)(b * 4 + hkv) * 131072;
    const float* Vg = Vpg + (size_t)(b * 4 + hkv) * 131072;
    const float QSC = 0.125f * LOG2E;

    // Q fragments (pre-rounded tf32 in Qb; rescale by QSC then re-round)
    unsigned qf[8][4];
    #pragma unroll
    for (int kc = 0; kc < 8; kc++) {
        qf[kc][0] = f2tf(qp[(size_t)r * Cq + kc * 8 + c] * QSC);
        qf[kc][1] = f2tf(qp[(size_t)(r + 8) * Cq + kc * 8 + c] * QSC);
        qf[kc][2] = f2tf(qp[(size_t)r * Cq + kc * 8 + c + 4] * QSC);
        qf[kc][3] = f2tf(qp[(size_t)(r + 8) * Cq + kc * 8 + c + 4] * QSC);
    }

    // tile loaders: 1024 16B-chunks per tile, 4 per thread
    auto issueK = [&](int kt, int buf) {
        float* Kd = sm + buf * KBUF;
        #pragma unroll
        for (int l = 0; l < 4; l++) {
            int q = l * 256 + t;
            int plane = q >> 8, kvo = (q >> 2) & 63, u = q & 3;
            cp_async16(&Kd[plane * PLANE_STRIDE + kvo * 20 + 4 * u],
                       Kg + ((size_t)plane * 2048 + kt * 64 + kvo) * 16 + 4 * u);
        }
    };
    auto issueV = [&](int kt) {
        float* Vd = sm + VS_OFF4;
        #pragma unroll
        for (int l = 0; l < 4; l++) {
            int q = l * 256 + t;
            int plane = q >> 8, d = (q >> 2) & 63, u = q & 3;
            cp_async16(&Vd[plane * PLANE_STRIDE + d * 20 + 4 * u],
                       Vg + ((size_t)plane * 64 + d) * 512 + kt * 16 + 4 * u);
        }
    };

    issueK(0, 0); issueV(0); CP_COMMIT;
    CP_WAIT0;
    __syncthreads();
    issueK(1, 1); CP_COMMIT;

    float of[8][4];
    #pragma unroll
    for (int nt = 0; nt < 8; nt++)
        #pragma unroll
        for (int i = 0; i < 4; i++) of[nt][i] = 0.f;
    float m0 = -1e30f, m1 = -1e30f, l0 = 0.f, l1 = 0.f;
    float* Ps = sm + PS_OFF4;

    for (int kt = 0; kt < 32; kt++) {
        // ensure K[kt] arrived, make visible
        if (kt == 31) { CP_WAIT1; } else { CP_WAIT2; }
        __syncthreads();
        const float* Kc = sm + (kt & 1) * KBUF + c * PLANE_STRIDE;

        // S = Q K^T (log2 domain): per nt, 4x LDS.128 covering all 8 k-octets
        float sf[8][4];
        #pragma unroll
        for (int nt = 0; nt < 8; nt++)
            #pragma unroll
            for (int i = 0; i < 4; i++) sf[nt][i] = 0.f;
        #pragma unroll
        for (int kc2 = 0; kc2 < 4; kc2++) {
            #pragma unroll
            for (int nt = 0; nt < 8; nt++) {
                float4 k4 = *(const float4*)&Kc[(nt * 8 + r) * 20 + kc2 * 4];
                unsigned bf0[2] = {__float_as_uint(k4.x), __float_as_uint(k4.y)};
                mma_tf32(sf[nt], qf[2 * kc2], bf0);
                unsigned bf1[2] = {__float_as_uint(k4.z), __float_as_uint(k4.w)};
                mma_tf32(sf[nt], qf[2 * kc2 + 1], bf1);
            }
        }

        // online softmax in registers
        float mx0 = -1e30f, mx1 = -1e30f;
        #pragma unroll
        for (int nt = 0; nt < 8; nt++) {
            mx0 = fmaxf(mx0, fmaxf(sf[nt][0], sf[nt][1]));
            mx1 = fmaxf(mx1, fmaxf(sf[nt][2], sf[nt][3]));
        }
        mx0 = fmaxf(mx0, __shfl_xor_sync(0xffffffffu, mx0, 1));
        mx0 = fmaxf(mx0, __shfl_xor_sync(0xffffffffu, mx0, 2));
        mx1 = fmaxf(mx1, __shfl_xor_sync(0xffffffffu, mx1, 1));
        mx1 = fmaxf(mx1, __shfl_xor_sync(0xffffffffu, mx1, 2));
        float mn0 = fmaxf(m0, mx0), mn1 = fmaxf(m1, mx1);
        float sc0 = ex2(m0 - mn0), sc1 = ex2(m1 - mn1);
        float su0 = 0.f, su1 = 0.f;
        #pragma unroll
        for (int nt = 0; nt < 8; nt++) {
            sf[nt][0] = ex2(sf[nt][0] - mn0);
            sf[nt][1] = ex2(sf[nt][1] - mn0);
            sf[nt][2] = ex2(sf[nt][2] - mn1);
            sf[nt][3] = ex2(sf[nt][3] - mn1);
            su0 += sf[nt][0] + sf[nt][1];
            su1 += sf[nt][2] + sf[nt][3];
        }
        su0 += __shfl_xor_sync(0xffffffffu, su0, 1);
        su0 += __shfl_xor_sync(0xffffffffu, su0, 2);
        su1 += __shfl_xor_sync(0xffffffffu, su1, 1);
        su1 += __shfl_xor_sync(0xffffffffu, su1, 2);
        l0 = l0 * sc0 + su0; l1 = l1 * sc1 + su1;
        m0 = mn0; m1 = mn1;
        #pragma unroll
        for (int nt = 0; nt < 8; nt++) {
            of[nt][0] *= sc0; of[nt][1] *= sc0;
            of[nt][2] *= sc1; of[nt][3] *= sc1;
        }

        // P -> per-warp smem slice
        #pragma unroll
        for (int nt = 0; nt < 8; nt++) {
            *(float2*)&Ps[(wr + r) * 68 + nt * 8 + 2 * c] =
                make_float2(sf[nt][0], sf[nt][1]);
            *(float2*)&Ps[(wr + r + 8) * 68 + nt * 8 + 2 * c] =
                make_float2(sf[nt][2], sf[nt][3]);
        }
        __syncwarp();

        // ensure V[kt] arrived, make visible (also: all warps past S on K[kt])
        if (kt == 31) { CP_WAIT0; } else { CP_WAIT1; }
        __syncthreads();
        const float* Vc = sm + VS_OFF4 + c * PLANE_STRIDE;

        // O += P V : per (kc-pair, nt), 1x LDS.128 V + 2 mma
        #pragma unroll
        for (int kc2 = 0; kc2 < 4; kc2++) {
            unsigned pf0[4], pf1[4];
            pf0[0] = f2tf(Ps[(wr + r) * 68 + kc2 * 16 + c]);
            pf0[1] = f2tf(Ps[(wr + r + 8) * 68 + kc2 * 16 + c]);
            pf0[2] = f2tf(Ps[(wr + r) * 68 + kc2 * 16 + c + 4]);
            pf0[3] = f2tf(Ps[(wr + r + 8) * 68 + kc2 * 16 + c + 4]);
            pf1[0] = f2tf(Ps[(wr + r) * 68 + kc2 * 16 + 8 + c]);
            pf1[1] = f2tf(Ps[(wr + r + 8) * 68 + kc2 * 16 + 8 + c]);
            pf1[2] = f2tf(Ps[(wr + r) * 68 + kc2 * 16 + 8 + c + 4]);
            pf1[3] = f2tf(Ps[(wr + r + 8) * 68 + kc2 * 16 + 8 + c + 4]);
            #pragma unroll
            for (int nt = 0; nt < 8; nt++) {
                float4 v4 = *(const float4*)&Vc[(nt * 8 + r) * 20 + kc2 * 4];
                unsigned bf0[2] = {__float_as_uint(v4.x), __float_as_uint(v4.y)};
                mma_tf32(of[nt], pf0, bf0);
                unsigned bf1[2] = {__float_as_uint(v4.z), __float_as_uint(v4.w)};
                mma_tf32(of[nt], pf1, bf1);
            }
        }
        __syncthreads();  // V buffer free

        if (kt + 1 < 32) { issueV(kt + 1); CP_COMMIT; }
        if (kt + 2 < 32) { issueK(kt + 2, kt & 1); CP_COMMIT; }
    }

    // epilogue: round O to tf32 (feeds out-proj GEMM)
    float inv0 = 1.f / l0, inv1 = 1.f / l1;
    size_t row0 = (size_t)(b * Nq + qt * 128 + wr + r);
    #pragma unroll
    for (int nt = 0; nt < 8; nt++) {
        int col = h * 64 + nt * 8 + 2 * c;
        *(float2*)&O[row0 * Cq + col] =
            make_float2(rnd_tf(of[nt][0] * inv0), rnd_tf(of[nt][1] * inv0));
        *(float2*)&O[(row0 + 8) * Cq + col] =
            make_float2(rnd_tf(of[nt][2] * inv1), rnd_tf(of[nt][3] * inv1));
    }
}

// ---------------------------------------------------------------------------
extern "C" void kernel_launch(void* const* d_in, const int* in_sizes, int n_in,
                              void* d_out, int out_size)
{
    const float* x   = (const float*)d_in[0];
    const float* rw  = (const float*)d_in[1];
    const float* rb  = (const float*)d_in[2];
    const float* wq  = (const float*)d_in[3];
    const float* bq  = (const float*)d_in[4];
    const float* wk  = (const float*)d_in[5];
    const float* bk  = (const float*)d_in[6];
    const float* wv  = (const float*)d_in[7];
    const float* bv  = (const float*)d_in[8];
    const float* wo  = (const float*)d_in[9];
    const float* bo  = (const float*)d_in[10];
    float* out = (float*)d_out;

    float* base;
    cudaGetSymbolAddress((void**)&base, g_scratch);
    float* xg   = base + XG_OFF;
    float* qb   = base + QB_OFF;
    float* kp   = base + KP_OFF;
    float* vp   = base + VP_OFF;
    float* ob   = base + OB_OFF;
    float* wqkv = base + WQKV_OFF;
    float* wor  = base + WO_OFF;
    float* bqkv = base + BQKV_OFF;
    float* gate = base + GATE_OFF;
    float* thr  = base + THR_OFF;

    cudaFuncSetAttribute(attn4, cudaFuncAttributeMaxDynamicSharedMemorySize, ATTN_SMEM);

    gate_kernel<<<TOK / 8, 256>>>(x, rw, rb, gate);
    topk_kernel<<<Bq, 1024>>>(gate, thr);
    xg_kernel<<<(TOK * Cq) / (4 * 256), 256>>>((const float4*)x, gate, thr, (float4*)xg);
    pack_kernel<<<(1024 * 384) / 256, 256>>>(wq, wk, wv, bq, bk, bv, wqkv, bqkv);
    round_kernel<<<(1024 * 256) / 256, 256>>>((const float4*)wo, (float4*)wor);

    // fused QKV projection -> Qb / Kp / Vp
    gemm_tf32<1><<<dim3(1536 / 128, TOK / 128), 256>>>(xg, wqkv, bqkv, qb, kp, vp, TOK, 1536, Cq);

    attn4<<<dim3(Nq / 128, Hq, Bq), 256, ATTN_SMEM>>>(qb, kp, vp, ob);

    // output projection (fp32 out)
    gemm_tf32<0><<<dim3(Cq / 128, TOK / 128), 256>>>(ob, wor, bo, out, nullptr, nullptr, TOK, Cq, Cq);
}